// round 1
// baseline (speedup 1.0000x reference)
#include <cuda_runtime.h>
#include <cstdint>

// ---------------------------------------------------------------------------
// EncoderLayer: x -> attn(mask) -> +x -> LN1 -> FFN(relu) -> +h -> LN2
// B=4, S=1024, D=1024, H=16, hd=64, FFN=4096, fp32 throughout.
// ---------------------------------------------------------------------------

#define Dm   1024
#define Hh   16
#define HD   64
#define FFNm 4096
#define Bb   4
#define Ss   1024
#define MTOT (Bb*Ss)          // 4096 rows
#define NEGV (-1e9f)
#define EPSV (1e-12f)
#define SCALE (0.125f)        // hd^-0.5 = 1/8

// ------------------------------- scratch ----------------------------------
__device__ float g_q[Bb*Hh*Ss*HD];      // [b,h,s,d]  (pre-scaled)
__device__ float g_kk[Bb*Hh*Ss*HD];
__device__ float g_v[Bb*Hh*Ss*HD];
__device__ float g_scores[(size_t)Bb*Hh*Ss*Ss];   // 256 MB
__device__ float g_ctx[MTOT*Dm];
__device__ float g_res1[MTOT*Dm];
__device__ float g_h[MTOT*Dm];
__device__ float g_ff1[(size_t)MTOT*FFNm];
__device__ float g_res2[MTOT*Dm];

// ------------------------------ reductions --------------------------------
__device__ __forceinline__ float blockReduceSum(float v, float* sh) {
    __syncthreads();
    int lane = threadIdx.x & 31, w = threadIdx.x >> 5;
    #pragma unroll
    for (int o = 16; o; o >>= 1) v += __shfl_xor_sync(0xffffffffu, v, o);
    if (lane == 0) sh[w] = v;
    __syncthreads();
    if (threadIdx.x == 0) {
        float s = 0.f;
        #pragma unroll
        for (int i = 0; i < 8; i++) s += sh[i];
        sh[0] = s;
    }
    __syncthreads();
    return sh[0];
}

__device__ __forceinline__ float blockReduceMax(float v, float* sh) {
    __syncthreads();
    int lane = threadIdx.x & 31, w = threadIdx.x >> 5;
    #pragma unroll
    for (int o = 16; o; o >>= 1) v = fmaxf(v, __shfl_xor_sync(0xffffffffu, v, o));
    if (lane == 0) sh[w] = v;
    __syncthreads();
    if (threadIdx.x == 0) {
        float s = sh[0];
        #pragma unroll
        for (int i = 1; i < 8; i++) s = fmaxf(s, sh[i]);
        sh[0] = s;
    }
    __syncthreads();
    return sh[0];
}

// ------------------------------- GEMM NT ----------------------------------
// C[M,N] = A[M,K] @ B[N,K]^T (+ bias) with per-mode epilogue.
// BM=BN=128, BK=32, 256 threads, 8x8 per thread. Batched via blockIdx.z.
// MODE 0: scatter to Q(scaled)/K/V          (qkv projection)
// MODE 1: key-mask epilogue -> scores       (batched, K=64)
// MODE 2: relu -> C                         (ffn1)
// MODE 3: + residual -> C                   (out proj, ffn2)
template<int MODE>
__global__ __launch_bounds__(256)
void gemm_nt(const float* __restrict__ A, const float* __restrict__ Bm,
             const float* __restrict__ bias, float* __restrict__ C,
             int M, int N, int K,
             long sAb, long sBb, long sCb,
             const float* __restrict__ resid,
             const int* __restrict__ mask,
             float* __restrict__ qo, float* __restrict__ ko, float* __restrict__ vo)
{
    const int z  = blockIdx.z;
    A  += (long)z * sAb;
    Bm += (long)z * sBb;
    float* Cz = C ? (C + (long)z * sCb) : nullptr;

    const int tid = threadIdx.x;
    const int m0 = blockIdx.y * 128, n0 = blockIdx.x * 128;
    const int tx = tid & 15, ty = tid >> 4;

    __shared__ float As[32][132];
    __shared__ float Bs[32][132];

    float acc[8][8];
    #pragma unroll
    for (int i = 0; i < 8; i++)
        #pragma unroll
        for (int j = 0; j < 8; j++) acc[i][j] = 0.f;

    for (int k0 = 0; k0 < K; k0 += 32) {
        #pragma unroll
        for (int i = 0; i < 4; i++) {
            int f = tid + i * 256;          // float4 id 0..1023
            int row = f >> 3, c4 = f & 7;
            float4 a4 = *(const float4*)(A  + (long)(m0 + row) * K + k0 + c4 * 4);
            As[c4*4+0][row] = a4.x; As[c4*4+1][row] = a4.y;
            As[c4*4+2][row] = a4.z; As[c4*4+3][row] = a4.w;
            float4 b4 = *(const float4*)(Bm + (long)(n0 + row) * K + k0 + c4 * 4);
            Bs[c4*4+0][row] = b4.x; Bs[c4*4+1][row] = b4.y;
            Bs[c4*4+2][row] = b4.z; Bs[c4*4+3][row] = b4.w;
        }
        __syncthreads();
        #pragma unroll 16
        for (int kk = 0; kk < 32; kk++) {
            float af[8], bf[8];
            *(float4*)&af[0] = *(const float4*)&As[kk][ty*8];
            *(float4*)&af[4] = *(const float4*)&As[kk][ty*8+4];
            *(float4*)&bf[0] = *(const float4*)&Bs[kk][tx*8];
            *(float4*)&bf[4] = *(const float4*)&Bs[kk][tx*8+4];
            #pragma unroll
            for (int i = 0; i < 8; i++)
                #pragma unroll
                for (int j = 0; j < 8; j++)
                    acc[i][j] = fmaf(af[i], bf[j], acc[i][j]);
        }
        __syncthreads();
    }

    #pragma unroll
    for (int i = 0; i < 8; i++) {
        int m = m0 + ty * 8 + i;
        #pragma unroll
        for (int j = 0; j < 8; j++) {
            int n = n0 + tx * 8 + j;
            float val = acc[i][j] + (bias ? bias[n] : 0.f);
            if (MODE == 0) {
                int b = m >> 10, s = m & 1023;
                int which = n >> 10, hm = n & 1023;
                int h = hm >> 6, d = hm & 63;
                long idx = ((long)(b * Hh + h) * Ss + s) * HD + d;
                if (which == 0)      qo[idx] = val * SCALE;
                else if (which == 1) ko[idx] = val;
                else                 vo[idx] = val;
            } else if (MODE == 1) {
                Cz[(long)m * N + n] = mask[(long)z * Ss + n] ? val : NEGV;
            } else if (MODE == 2) {
                Cz[(long)m * N + n] = fmaxf(val, 0.f);
            } else { // MODE 3
                Cz[(long)m * N + n] = val + resid[(long)m * N + n];
            }
        }
    }
}

// ------------------------------- P @ V (NN) -------------------------------
// ctx[b,s, h*64+d] = sum_j P[z][s][j] * V[z][j][d], z = b*H+h.
// BM=128, BN=64, BK=32, 256 threads, 8x4 per thread. grid (1, S/128, B*H).
__global__ __launch_bounds__(256)
void gemm_pv(const float* __restrict__ P, const float* __restrict__ V,
             float* __restrict__ ctx)
{
    const int z = blockIdx.z;
    const int b = z >> 4, h = z & 15;
    const float* Pz = P + (long)z * Ss * Ss;
    const float* Vz = V + (long)z * Ss * HD;
    const int m0 = blockIdx.y * 128;
    const int tid = threadIdx.x;
    const int tx = tid & 15, ty = tid >> 4;

    __shared__ float Ps[32][132];
    __shared__ float Vs[32][68];

    float acc[8][4];
    #pragma unroll
    for (int i = 0; i < 8; i++)
        #pragma unroll
        for (int j = 0; j < 4; j++) acc[i][j] = 0.f;

    for (int k0 = 0; k0 < Ss; k0 += 32) {
        #pragma unroll
        for (int i = 0; i < 4; i++) {
            int f = tid + i * 256;
            int row = f >> 3, c4 = f & 7;
            float4 p4 = *(const float4*)(Pz + (long)(m0 + row) * Ss + k0 + c4 * 4);
            Ps[c4*4+0][row] = p4.x; Ps[c4*4+1][row] = p4.y;
            Ps[c4*4+2][row] = p4.z; Ps[c4*4+3][row] = p4.w;
        }
        #pragma unroll
        for (int i = 0; i < 2; i++) {
            int f = tid + i * 256;
            int row = f >> 4, c4 = f & 15;
            *(float4*)&Vs[row][c4*4] = *(const float4*)(Vz + (long)(k0 + row) * HD + c4 * 4);
        }
        __syncthreads();
        #pragma unroll 16
        for (int kk = 0; kk < 32; kk++) {
            float pf[8], vf[4];
            *(float4*)&pf[0] = *(const float4*)&Ps[kk][ty*8];
            *(float4*)&pf[4] = *(const float4*)&Ps[kk][ty*8+4];
            *(float4*)&vf[0] = *(const float4*)&Vs[kk][tx*4];
            #pragma unroll
            for (int i = 0; i < 8; i++)
                #pragma unroll
                for (int j = 0; j < 4; j++)
                    acc[i][j] = fmaf(pf[i], vf[j], acc[i][j]);
        }
        __syncthreads();
    }

    #pragma unroll
    for (int i = 0; i < 8; i++) {
        int s = m0 + ty * 8 + i;
        #pragma unroll
        for (int j = 0; j < 4; j++) {
            int d = tx * 4 + j;
            ctx[((long)(b * Ss + s)) * Dm + h * 64 + d] = acc[i][j];
        }
    }
}

// ------------------------------- softmax ----------------------------------
// One block per attention row of 1024 scores. 256 threads, float4 each.
__global__ __launch_bounds__(256)
void softmax_k(float* __restrict__ sc)
{
    long row = blockIdx.x;
    float4* p = (float4*)(sc + row * (long)Ss);
    int t = threadIdx.x;
    __shared__ float sh[8];

    float4 v = p[t];
    float mx = fmaxf(fmaxf(v.x, v.y), fmaxf(v.z, v.w));
    mx = blockReduceMax(mx, sh);

    float e0 = __expf(v.x - mx), e1 = __expf(v.y - mx);
    float e2 = __expf(v.z - mx), e3 = __expf(v.w - mx);
    float s = blockReduceSum(e0 + e1 + e2 + e3, sh);
    float inv = 1.f / s;
    p[t] = make_float4(e0 * inv, e1 * inv, e2 * inv, e3 * inv);
}

// ------------------------------ layernorm ---------------------------------
// One block per row of D=1024. Biased variance, matches reference.
__global__ __launch_bounds__(256)
void layernorm_k(const float* __restrict__ in, const float* __restrict__ g,
                 const float* __restrict__ be, float* __restrict__ out)
{
    long row = blockIdx.x;
    const float4* p = (const float4*)(in + row * (long)Dm);
    int t = threadIdx.x;
    __shared__ float sh[8];

    float4 v = p[t];
    float s  = v.x + v.y + v.z + v.w;
    float sq = v.x*v.x + v.y*v.y + v.z*v.z + v.w*v.w;
    s  = blockReduceSum(s, sh);
    sq = blockReduceSum(sq, sh);

    float mean = s * (1.f / Dm);
    float var  = sq * (1.f / Dm) - mean * mean;
    float inv  = rsqrtf(var + EPSV);

    float4 gg = ((const float4*)g)[t];
    float4 bb = ((const float4*)be)[t];
    float4 o;
    o.x = gg.x * (v.x - mean) * inv + bb.x;
    o.y = gg.y * (v.y - mean) * inv + bb.y;
    o.z = gg.z * (v.z - mean) * inv + bb.z;
    o.w = gg.w * (v.w - mean) * inv + bb.w;
    ((float4*)(out + row * (long)Dm))[t] = o;
}

// ------------------------------- launcher ---------------------------------
static float* symaddr(const void* sym) {
    void* p = nullptr;
    cudaGetSymbolAddress(&p, sym);
    return (float*)p;
}

extern "C" void kernel_launch(void* const* d_in, const int* in_sizes, int n_in,
                              void* d_out, int out_size)
{
    const float* x    = (const float*)d_in[0];
    const int*   mask = (const int*)  d_in[1];   // bool -> int32 in harness
    const float* Wqkv = (const float*)d_in[2];
    const float* bqkv = (const float*)d_in[3];
    const float* Wo   = (const float*)d_in[4];
    const float* bo   = (const float*)d_in[5];
    const float* W1   = (const float*)d_in[6];
    const float* b1   = (const float*)d_in[7];
    const float* W2   = (const float*)d_in[8];
    const float* b2   = (const float*)d_in[9];
    const float* g1   = (const float*)d_in[10];
    const float* be1  = (const float*)d_in[11];
    const float* g2   = (const float*)d_in[12];
    const float* be2  = (const float*)d_in[13];
    float* out = (float*)d_out;

    float* q   = symaddr(g_q);
    float* kk  = symaddr(g_kk);
    float* v   = symaddr(g_v);
    float* sc  = symaddr(g_scores);
    float* ctx = symaddr(g_ctx);
    float* r1  = symaddr(g_res1);
    float* hbuf= symaddr(g_h);
    float* f1  = symaddr(g_ff1);
    float* r2  = symaddr(g_res2);

    // 1) QKV projection: [4096,1024] @ [3072,1024]^T, scatter to q/k/v
    gemm_nt<0><<<dim3(24, 32, 1), 256>>>(x, Wqkv, bqkv, nullptr,
        MTOT, 3*Dm, Dm, 0, 0, 0, nullptr, nullptr, q, kk, v);

    // 2) scores = q @ k^T (q pre-scaled), key mask -> NEG
    gemm_nt<1><<<dim3(8, 8, Bb*Hh), 256>>>(q, kk, nullptr, sc,
        Ss, Ss, HD, (long)Ss*HD, (long)Ss*HD, (long)Ss*Ss,
        nullptr, mask, nullptr, nullptr, nullptr);

    // 3) row softmax over 1024 keys
    softmax_k<<<Bb*Hh*Ss, 256>>>(sc);

    // 4) ctx = P @ V  (transposed back to [b,s,D] on write)
    gemm_pv<<<dim3(1, 8, Bb*Hh), 256>>>(sc, v, ctx);

    // 5) out proj + residual(x)
    gemm_nt<3><<<dim3(8, 32, 1), 256>>>(ctx, Wo, bo, r1,
        MTOT, Dm, Dm, 0, 0, 0, x, nullptr, nullptr, nullptr, nullptr);

    // 6) LN1
    layernorm_k<<<MTOT, 256>>>(r1, g1, be1, hbuf);

    // 7) FFN1 + relu: [4096,1024] @ [4096,1024]^T
    gemm_nt<2><<<dim3(32, 32, 1), 256>>>(hbuf, W1, b1, f1,
        MTOT, FFNm, Dm, 0, 0, 0, nullptr, nullptr, nullptr, nullptr, nullptr);

    // 8) FFN2 + residual(h): [4096,4096] @ [1024,4096]^T
    gemm_nt<3><<<dim3(8, 32, 1), 256>>>(f1, W2, b2, r2,
        MTOT, Dm, FFNm, 0, 0, 0, hbuf, nullptr, nullptr, nullptr, nullptr);

    // 9) LN2 -> output
    layernorm_k<<<MTOT, 256>>>(r2, g2, be2, out);
}

// round 3
// speedup vs baseline: 2.2579x; 2.2579x over previous
#include <cuda_runtime.h>
#include <cuda_fp16.h>
#include <cstdint>

// ---------------------------------------------------------------------------
// EncoderLayer via legacy tensor cores (mma.sync m16n8k16 fp16, f32 acc),
// split-fp16 (hi+lo, 3 MMA terms) for fp32-grade accuracy.
// B=4, S=1024, D=1024, H=16, hd=64, FFN=4096.
// ---------------------------------------------------------------------------

#define Dm   1024
#define Hh   16
#define HD   64
#define FFNm 4096
#define Bb   4
#define Ss   1024
#define MTOT (Bb*Ss)
#define NEGV (-1e9f)
#define EPSV (1e-12f)

// ------------------------------ ptx helpers -------------------------------
__device__ __forceinline__ uint32_t smem_u32(const void* p) {
    uint32_t a;
    asm("{ .reg .u64 t; cvta.to.shared.u64 t, %1; cvt.u32.u64 %0, t; }"
        : "=r"(a) : "l"(p));
    return a;
}

#define CP16(dst, src) \
    asm volatile("cp.async.cg.shared.global [%0], [%1], 16;" :: "r"(dst), "l"(src))
#define CP_COMMIT() asm volatile("cp.async.commit_group;" ::: "memory")
#define CP_WAIT1()  asm volatile("cp.async.wait_group 1;" ::: "memory")

#define LDSM4(r, addr) \
    asm volatile("ldmatrix.sync.aligned.m8n8.x4.shared.b16 {%0,%1,%2,%3}, [%4];" \
        : "=r"((r)[0]), "=r"((r)[1]), "=r"((r)[2]), "=r"((r)[3]) : "r"(addr))
#define LDSM2(r, addr) \
    asm volatile("ldmatrix.sync.aligned.m8n8.x2.shared.b16 {%0,%1}, [%2];" \
        : "=r"((r)[0]), "=r"((r)[1]) : "r"(addr))

#define MMA(c, a, b) \
    asm volatile("mma.sync.aligned.m16n8k16.row.col.f32.f16.f16.f32 " \
        "{%0,%1,%2,%3},{%4,%5,%6,%7},{%8,%9},{%0,%1,%2,%3};" \
        : "+f"((c)[0]), "+f"((c)[1]), "+f"((c)[2]), "+f"((c)[3]) \
        : "r"((a)[0]), "r"((a)[1]), "r"((a)[2]), "r"((a)[3]), "r"((b)[0]), "r"((b)[1]))

// ------------------------------- scratch ----------------------------------
__device__ __half g_xhi[MTOT*Dm],    g_xlo[MTOT*Dm];
__device__ __half g_Wqkvh[3*Dm*Dm],  g_Wqkvl[3*Dm*Dm];
__device__ __half g_Woh[Dm*Dm],      g_Wol[Dm*Dm];
__device__ __half g_W1h[FFNm*Dm],    g_W1l[FFNm*Dm];
__device__ __half g_W2h[Dm*FFNm],    g_W2l[Dm*FFNm];
__device__ __half g_qh[Bb*Hh*Ss*HD], g_ql[Bb*Hh*Ss*HD];
__device__ __half g_kh[Bb*Hh*Ss*HD], g_kl[Bb*Hh*Ss*HD];
__device__ __half g_vth[Bb*Hh*Ss*HD], g_vtl[Bb*Hh*Ss*HD];   // [z][d][s]
__device__ float  g_scores[(size_t)Bb*Hh*Ss*Ss];
__device__ __half g_ph[(size_t)Bb*Hh*Ss*Ss], g_pl[(size_t)Bb*Hh*Ss*Ss];
__device__ __half g_ctxh[MTOT*Dm],   g_ctxl[MTOT*Dm];
__device__ float  g_r1[MTOT*Dm];
__device__ float  g_h[MTOT*Dm];
__device__ __half g_hh[MTOT*Dm],     g_hl[MTOT*Dm];
__device__ __half g_f1h[(size_t)MTOT*FFNm], g_f1l[(size_t)MTOT*FFNm];
__device__ float  g_r2[MTOT*Dm];

// ------------------------------- split utils ------------------------------
__device__ __forceinline__ void splitpair(float a, float b, uint32_t& h, uint32_t& l) {
    __half ha = __float2half_rn(a), hb = __float2half_rn(b);
    __half la = __float2half_rn(a - __half2float(ha));
    __half lb = __float2half_rn(b - __half2float(hb));
    h = (uint32_t)__half_as_ushort(ha) | ((uint32_t)__half_as_ushort(hb) << 16);
    l = (uint32_t)__half_as_ushort(la) | ((uint32_t)__half_as_ushort(lb) << 16);
}

// ------------------------------- GEMM (HMMA) -------------------------------
// C[M,N] = A[M,K] @ B[N,K]^T, split-fp16 operands, fp32 accumulators.
// BM=128, BK=32, 256 threads = 8 warps (2 Mwarps x 4 Nwarps), warp tile 64 x BN/4.
// 3-stage cp.async pipeline; smem rows padded 32->40 halves for conflict-free LDSM.
// MODE 0: qkv scatter (q scaled+split, k split, v transposed+split)
// MODE 1: key-mask -> scores fp32
// MODE 2: ctx split -> ctxh/ctxl
// MODE 3/5: +bias +resid -> fp32
// MODE 4: relu+bias -> split halves
template<int BN, int MODE>
__global__ __launch_bounds__(256)
void mma_gemm(const __half* __restrict__ Ahi, const __half* __restrict__ Alo,
              const __half* __restrict__ Bhi, const __half* __restrict__ Blo,
              const float* __restrict__ bias, int K, long sA, long sB,
              const int* __restrict__ mask,
              const float* __restrict__ resid,
              int Nc, float* __restrict__ Cf, long sC,
              __half* __restrict__ Chi, __half* __restrict__ Clo,
              __half* __restrict__ qh, __half* __restrict__ ql,
              __half* __restrict__ kh, __half* __restrict__ kl,
              __half* __restrict__ vh, __half* __restrict__ vl)
{
    constexpr int A_BYTES = 128 * 80;       // 128 rows x 40 halves
    constexpr int B_BYTES = BN * 80;
    constexpr int STAGE   = 2 * A_BYTES + 2 * B_BYTES;
    constexpr int WN = BN / 4;              // warp N tile
    constexpr int NT = WN / 8;              // n8 tiles per warp

    const int tid = threadIdx.x;
    const int wid = tid >> 5, l = tid & 31;
    const int wm = wid >> 2, wn = wid & 3;
    const int z  = blockIdx.z;
    const int m0 = blockIdx.y * 128;
    const int n0 = blockIdx.x * BN;

    const __half *pAh = Ahi + (size_t)z * sA, *pAl = Alo + (size_t)z * sA;
    const __half *pBh = Bhi + (size_t)z * sB, *pBl = Blo + (size_t)z * sB;

    extern __shared__ char dsm[];
    __shared__ int s_mask[128];
    const uint32_t smem_base = smem_u32(dsm);

    if (MODE == 1 && tid < BN) s_mask[tid] = mask[(size_t)z * Ss + n0 + tid];

    // ldmatrix smem offsets (within stage), per fragment tile
    uint32_t aoff[4];
    #pragma unroll
    for (int mt = 0; mt < 4; mt++)
        aoff[mt] = (uint32_t)((wm*64 + mt*16 + (l & 15)) * 80 + (l >> 4) * 16);
    uint32_t boff[NT];
    #pragma unroll
    for (int nt = 0; nt < NT; nt++)
        boff[nt] = (uint32_t)((wn*WN + nt*8 + (l & 7)) * 80 + ((l >> 3) & 1) * 16);

    float acc[4][NT][4];
    #pragma unroll
    for (int mt = 0; mt < 4; mt++)
        #pragma unroll
        for (int nt = 0; nt < NT; nt++)
            #pragma unroll
            for (int j = 0; j < 4; j++) acc[mt][nt][j] = 0.f;

    const int niter = K >> 5;

    auto load_stage = [&](int st, int k0) {
        uint32_t base = smem_base + st * STAGE;
        #pragma unroll
        for (int i = 0; i < 2; i++) {            // A: 512 chunks
            int id = tid + (i << 8);
            int r = id >> 2, c = id & 3;
            size_t g = (size_t)(m0 + r) * K + k0 + c * 8;
            uint32_t d = base + r * 80 + c * 16;
            CP16(d, pAh + g);
            CP16(d + A_BYTES, pAl + g);
        }
        #pragma unroll
        for (int i = 0; i < BN / 64; i++) {      // B: BN*4 chunks
            int id = tid + (i << 8);
            int r = id >> 2, c = id & 3;
            size_t g = (size_t)(n0 + r) * K + k0 + c * 8;
            uint32_t d = base + 2 * A_BYTES + r * 80 + c * 16;
            CP16(d, pBh + g);
            CP16(d + B_BYTES, pBl + g);
        }
    };

    // prologue: stages 0,1
    load_stage(0, 0);  CP_COMMIT();
    if (niter > 1) load_stage(1, 32);
    CP_COMMIT();

    for (int it = 0; it < niter; it++) {
        CP_WAIT1();
        __syncthreads();

        int pf = it + 2;
        if (pf < niter) load_stage(pf % 3, pf << 5);
        CP_COMMIT();

        const uint32_t sAb = smem_base + (it % 3) * STAGE;
        const uint32_t sBb = sAb + 2 * A_BYTES;
        #pragma unroll
        for (int ks = 0; ks < 2; ks++) {
            uint32_t ah[4][4], al[4][4];
            #pragma unroll
            for (int mt = 0; mt < 4; mt++) {
                uint32_t addr = sAb + aoff[mt] + ks * 32;
                LDSM4(ah[mt], addr);
                LDSM4(al[mt], addr + A_BYTES);
            }
            #pragma unroll
            for (int nt = 0; nt < NT; nt++) {
                uint32_t bh[2], bl[2];
                uint32_t baddr = sBb + boff[nt] + ks * 32;
                LDSM2(bh, baddr);
                LDSM2(bl, baddr + B_BYTES);
                #pragma unroll
                for (int mt = 0; mt < 4; mt++) {
                    MMA(acc[mt][nt], ah[mt], bh);
                    MMA(acc[mt][nt], ah[mt], bl);
                    MMA(acc[mt][nt], al[mt], bh);
                }
            }
        }
    }

    // ------------------------------ epilogue --------------------------------
    const int rbase = m0 + wm*64 + (l >> 2);
    const int cbase = n0 + wn*WN + 2*(l & 3);

    #pragma unroll
    for (int mt = 0; mt < 4; mt++) {
        #pragma unroll
        for (int nt = 0; nt < NT; nt++) {
            const int col = cbase + nt*8;
            #pragma unroll
            for (int half_ : {0, 1}) {
                const int row = rbase + mt*16 + half_*8;
                float v0 = acc[mt][nt][half_*2 + 0];
                float v1 = acc[mt][nt][half_*2 + 1];

                if (MODE == 0) {
                    float f0 = v0 + bias[col], f1 = v1 + bias[col + 1];
                    const int which = col >> 10;
                    const int hm = col & 1023;
                    const int hidx = hm >> 6, d = hm & 63;
                    const int b = row >> 10, s = row & 1023;
                    const int zz = (b << 4) + hidx;
                    if (which == 0) { f0 *= 0.125f; f1 *= 0.125f; }
                    if (which < 2) {
                        __half* th = (which == 0) ? qh : kh;
                        __half* tl = (which == 0) ? ql : kl;
                        size_t idx = ((size_t)zz * Ss + s) * 64 + d;
                        uint32_t hv, lv;
                        splitpair(f0, f1, hv, lv);
                        *(uint32_t*)(th + idx) = hv;
                        *(uint32_t*)(tl + idx) = lv;
                    } else {
                        size_t i0 = ((size_t)zz * 64 + d) * Ss + s;
                        __half h0 = __float2half_rn(f0), h1 = __float2half_rn(f1);
                        vh[i0] = h0;
                        vh[i0 + Ss] = h1;
                        vl[i0] = __float2half_rn(f0 - __half2float(h0));
                        vl[i0 + Ss] = __float2half_rn(f1 - __half2float(h1));
                    }
                } else if (MODE == 1) {
                    size_t idx = (size_t)z * sC + (size_t)row * Ss + col;
                    float2 o;
                    o.x = s_mask[col - n0]     ? v0 : NEGV;
                    o.y = s_mask[col - n0 + 1] ? v1 : NEGV;
                    *(float2*)(Cf + idx) = o;
                } else if (MODE == 2) {
                    const int b = z >> 4, hh2 = z & 15;
                    size_t idx = ((size_t)((b << 10) + row)) * Dm + (hh2 << 6) + col;
                    uint32_t hv, lv;
                    splitpair(v0, v1, hv, lv);
                    *(uint32_t*)(Chi + idx) = hv;
                    *(uint32_t*)(Clo + idx) = lv;
                } else if (MODE == 3 || MODE == 5) {
                    size_t idx = (size_t)row * Nc + col;
                    float2 rv = *(const float2*)(resid + idx);
                    float2 o;
                    o.x = v0 + bias[col]     + rv.x;
                    o.y = v1 + bias[col + 1] + rv.y;
                    *(float2*)(Cf + idx) = o;
                } else { // MODE 4
                    size_t idx = (size_t)row * Nc + col;
                    float f0 = fmaxf(v0 + bias[col], 0.f);
                    float f1 = fmaxf(v1 + bias[col + 1], 0.f);
                    uint32_t hv, lv;
                    splitpair(f0, f1, hv, lv);
                    *(uint32_t*)(Chi + idx) = hv;
                    *(uint32_t*)(Clo + idx) = lv;
                }
            }
        }
    }
}

// ------------------------------- aux kernels -------------------------------
__global__ __launch_bounds__(256)
void split_k(const float* __restrict__ in, __half* __restrict__ hi,
             __half* __restrict__ lo, int n4)
{
    int i = blockIdx.x * 256 + threadIdx.x;
    if (i >= n4) return;
    float4 v = ((const float4*)in)[i];
    uint2 hv, lv;
    splitpair(v.x, v.y, hv.x, lv.x);
    splitpair(v.z, v.w, hv.y, lv.y);
    ((uint2*)hi)[i] = hv;
    ((uint2*)lo)[i] = lv;
}

__device__ __forceinline__ float blockReduceSum(float v, float* sh) {
    __syncthreads();
    int lane = threadIdx.x & 31, w = threadIdx.x >> 5;
    #pragma unroll
    for (int o = 16; o; o >>= 1) v += __shfl_xor_sync(0xffffffffu, v, o);
    if (lane == 0) sh[w] = v;
    __syncthreads();
    if (threadIdx.x == 0) {
        float s = 0.f;
        #pragma unroll
        for (int i = 0; i < 8; i++) s += sh[i];
        sh[0] = s;
    }
    __syncthreads();
    return sh[0];
}
__device__ __forceinline__ float blockReduceMax(float v, float* sh) {
    __syncthreads();
    int lane = threadIdx.x & 31, w = threadIdx.x >> 5;
    #pragma unroll
    for (int o = 16; o; o >>= 1) v = fmaxf(v, __shfl_xor_sync(0xffffffffu, v, o));
    if (lane == 0) sh[w] = v;
    __syncthreads();
    if (threadIdx.x == 0) {
        float s = sh[0];
        #pragma unroll
        for (int i = 1; i < 8; i++) s = fmaxf(s, sh[i]);
        sh[0] = s;
    }
    __syncthreads();
    return sh[0];
}

// softmax over 1024 keys + split P to half hi/lo
__global__ __launch_bounds__(256)
void softmax_split(const float* __restrict__ sc,
                   __half* __restrict__ ph, __half* __restrict__ pl)
{
    size_t row = blockIdx.x;
    const float4* p = (const float4*)(sc + row * Ss);
    int t = threadIdx.x;
    __shared__ float sh[8];

    float4 v = p[t];
    float mx = fmaxf(fmaxf(v.x, v.y), fmaxf(v.z, v.w));
    mx = blockReduceMax(mx, sh);
    float e0 = __expf(v.x - mx), e1 = __expf(v.y - mx);
    float e2 = __expf(v.z - mx), e3 = __expf(v.w - mx);
    float s = blockReduceSum(e0 + e1 + e2 + e3, sh);
    float inv = 1.f / s;
    uint2 hv, lv;
    splitpair(e0 * inv, e1 * inv, hv.x, lv.x);
    splitpair(e2 * inv, e3 * inv, hv.y, lv.y);
    ((uint2*)(ph + row * Ss))[t] = hv;
    ((uint2*)(pl + row * Ss))[t] = lv;
}

// LayerNorm (biased variance); optionally emits split halves too
template<bool SPLIT>
__global__ __launch_bounds__(256)
void layernorm_k(const float* __restrict__ in, const float* __restrict__ g,
                 const float* __restrict__ be, float* __restrict__ out,
                 __half* __restrict__ ohi, __half* __restrict__ olo)
{
    size_t row = blockIdx.x;
    const float4* p = (const float4*)(in + row * Dm);
    int t = threadIdx.x;
    __shared__ float sh[8];

    float4 v = p[t];
    float s  = v.x + v.y + v.z + v.w;
    float sq = v.x*v.x + v.y*v.y + v.z*v.z + v.w*v.w;
    s  = blockReduceSum(s, sh);
    sq = blockReduceSum(sq, sh);
    float mean = s * (1.f / Dm);
    float var  = sq * (1.f / Dm) - mean * mean;
    float inv  = rsqrtf(var + EPSV);

    float4 gg = ((const float4*)g)[t];
    float4 bb = ((const float4*)be)[t];
    float4 o;
    o.x = gg.x * (v.x - mean) * inv + bb.x;
    o.y = gg.y * (v.y - mean) * inv + bb.y;
    o.z = gg.z * (v.z - mean) * inv + bb.z;
    o.w = gg.w * (v.w - mean) * inv + bb.w;
    ((float4*)(out + row * Dm))[t] = o;
    if (SPLIT) {
        uint2 hv, lv;
        splitpair(o.x, o.y, hv.x, lv.x);
        splitpair(o.z, o.w, hv.y, lv.y);
        ((uint2*)(ohi + row * Dm))[t] = hv;
        ((uint2*)(olo + row * Dm))[t] = lv;
    }
}

// ------------------------------- launcher ----------------------------------
static void* symaddr(const void* sym) {
    void* p = nullptr;
    cudaGetSymbolAddress(&p, sym);
    return p;
}

extern "C" void kernel_launch(void* const* d_in, const int* in_sizes, int n_in,
                              void* d_out, int out_size)
{
    const float* x    = (const float*)d_in[0];
    const int*   mask = (const int*)  d_in[1];
    const float* Wqkv = (const float*)d_in[2];
    const float* bqkv = (const float*)d_in[3];
    const float* Wo   = (const float*)d_in[4];
    const float* bo   = (const float*)d_in[5];
    const float* W1   = (const float*)d_in[6];
    const float* b1   = (const float*)d_in[7];
    const float* W2   = (const float*)d_in[8];
    const float* b2   = (const float*)d_in[9];
    const float* g1   = (const float*)d_in[10];
    const float* be1  = (const float*)d_in[11];
    const float* g2   = (const float*)d_in[12];
    const float* be2  = (const float*)d_in[13];
    float* out = (float*)d_out;

    __half* xhi = (__half*)symaddr(g_xhi);
    __half* xlo = (__half*)symaddr(g_xlo);
    __half* Wqh = (__half*)symaddr(g_Wqkvh);
    __half* Wql = (__half*)symaddr(g_Wqkvl);
    __half* Woh = (__half*)symaddr(g_Woh);
    __half* Wol = (__half*)symaddr(g_Wol);
    __half* W1h = (__half*)symaddr(g_W1h);
    __half* W1l = (__half*)symaddr(g_W1l);
    __half* W2h = (__half*)symaddr(g_W2h);
    __half* W2l = (__half*)symaddr(g_W2l);
    __half* qh  = (__half*)symaddr(g_qh);
    __half* ql  = (__half*)symaddr(g_ql);
    __half* kh  = (__half*)symaddr(g_kh);
    __half* kl  = (__half*)symaddr(g_kl);
    __half* vth = (__half*)symaddr(g_vth);
    __half* vtl = (__half*)symaddr(g_vtl);
    float*  sc  = (float*) symaddr(g_scores);
    __half* ph  = (__half*)symaddr(g_ph);
    __half* pl  = (__half*)symaddr(g_pl);
    __half* cxh = (__half*)symaddr(g_ctxh);
    __half* cxl = (__half*)symaddr(g_ctxl);
    float*  r1  = (float*) symaddr(g_r1);
    float*  hbf = (float*) symaddr(g_h);
    __half* hhi = (__half*)symaddr(g_hh);
    __half* hlo = (__half*)symaddr(g_hl);
    __half* f1h = (__half*)symaddr(g_f1h);
    __half* f1l = (__half*)symaddr(g_f1l);
    float*  r2  = (float*) symaddr(g_r2);

    constexpr int SM128 = 3 * (2*128*80 + 2*128*80);   // 122880
    constexpr int SM64  = 3 * (2*128*80 + 2*64*80);    //  92160
    cudaFuncSetAttribute(mma_gemm<128,0>, cudaFuncAttributeMaxDynamicSharedMemorySize, SM128);
    cudaFuncSetAttribute(mma_gemm<128,1>, cudaFuncAttributeMaxDynamicSharedMemorySize, SM128);
    cudaFuncSetAttribute(mma_gemm<64,2>,  cudaFuncAttributeMaxDynamicSharedMemorySize, SM64);
    cudaFuncSetAttribute(mma_gemm<128,3>, cudaFuncAttributeMaxDynamicSharedMemorySize, SM128);
    cudaFuncSetAttribute(mma_gemm<128,4>, cudaFuncAttributeMaxDynamicSharedMemorySize, SM128);
    cudaFuncSetAttribute(mma_gemm<128,5>, cudaFuncAttributeMaxDynamicSharedMemorySize, SM128);

    // 0) split inputs + weights to fp16 hi/lo
    split_k<<<(MTOT*Dm/4 + 255)/256, 256>>>(x,    xhi, xlo, MTOT*Dm/4);
    split_k<<<(3*Dm*Dm/4 + 255)/256, 256>>>(Wqkv, Wqh, Wql, 3*Dm*Dm/4);
    split_k<<<(Dm*Dm/4   + 255)/256, 256>>>(Wo,   Woh, Wol, Dm*Dm/4);
    split_k<<<(FFNm*Dm/4 + 255)/256, 256>>>(W1,   W1h, W1l, FFNm*Dm/4);
    split_k<<<(Dm*FFNm/4 + 255)/256, 256>>>(W2,   W2h, W2l, Dm*FFNm/4);

    // 1) QKV projection -> scatter split q (scaled) / k / v (transposed)
    mma_gemm<128,0><<<dim3(24, 32, 1), 256, SM128>>>(
        xhi, xlo, Wqh, Wql, bqkv, Dm, 0, 0,
        nullptr, nullptr, 3*Dm, nullptr, 0, nullptr, nullptr,
        qh, ql, kh, kl, vth, vtl);

    // 2) scores = q @ k^T with key mask
    mma_gemm<128,1><<<dim3(8, 8, Bb*Hh), 256, SM128>>>(
        qh, ql, kh, kl, nullptr, HD, (long)Ss*HD, (long)Ss*HD,
        mask, nullptr, Ss, sc, (long)Ss*Ss, nullptr, nullptr,
        nullptr, nullptr, nullptr, nullptr, nullptr, nullptr);

    // 3) softmax + split P
    softmax_split<<<Bb*Hh*Ss, 256>>>(sc, ph, pl);

    // 4) ctx = P @ V^T (V stored [z][d][s]) -> split ctx
    mma_gemm<64,2><<<dim3(1, 8, Bb*Hh), 256, SM64>>>(
        ph, pl, vth, vtl, nullptr, Ss, (long)Ss*Ss, (long)HD*Ss,
        nullptr, nullptr, Dm, nullptr, 0, cxh, cxl,
        nullptr, nullptr, nullptr, nullptr, nullptr, nullptr);

    // 5) out proj + residual(x)
    mma_gemm<128,3><<<dim3(8, 32, 1), 256, SM128>>>(
        cxh, cxl, Woh, Wol, bo, Dm, 0, 0,
        nullptr, x, Dm, r1, 0, nullptr, nullptr,
        nullptr, nullptr, nullptr, nullptr, nullptr, nullptr);

    // 6) LN1 (+ split h)
    layernorm_k<true><<<MTOT, 256>>>(r1, g1, be1, hbf, hhi, hlo);

    // 7) FFN1 + relu -> split f1
    mma_gemm<128,4><<<dim3(32, 32, 1), 256, SM128>>>(
        hhi, hlo, W1h, W1l, b1, Dm, 0, 0,
        nullptr, nullptr, FFNm, nullptr, 0, f1h, f1l,
        nullptr, nullptr, nullptr, nullptr, nullptr, nullptr);

    // 8) FFN2 + residual(h)
    mma_gemm<128,5><<<dim3(8, 32, 1), 256, SM128>>>(
        f1h, f1l, W2h, W2l, b2, FFNm, 0, 0,
        nullptr, hbf, Dm, r2, 0, nullptr, nullptr,
        nullptr, nullptr, nullptr, nullptr, nullptr, nullptr);

    // 9) LN2 -> output
    layernorm_k<false><<<MTOT, 256>>>(r2, g2, be2, out, nullptr, nullptr);
}

// round 4
// speedup vs baseline: 2.5212x; 1.1166x over previous
#include <cuda_runtime.h>
#include <cuda_fp16.h>
#include <cstdint>

// ---------------------------------------------------------------------------
// EncoderLayer via legacy tensor cores (mma.sync m16n8k16 fp16, f32 acc),
// split-fp16 (hi+lo, 3 MMA terms) for fp32-grade accuracy.
// Round 4: flash-fused attention (scores+mask+softmax+PV in one kernel,
// P kept in registers, zero attention-matrix memory traffic).
// ---------------------------------------------------------------------------

#define Dm   1024
#define Hh   16
#define HD   64
#define FFNm 4096
#define Bb   4
#define Ss   1024
#define MTOT (Bb*Ss)
#define NEGV (-1e9f)
#define EPSV (1e-12f)

// ------------------------------ ptx helpers -------------------------------
__device__ __forceinline__ uint32_t smem_u32(const void* p) {
    uint32_t a;
    asm("{ .reg .u64 t; cvta.to.shared.u64 t, %1; cvt.u32.u64 %0, t; }"
        : "=r"(a) : "l"(p));
    return a;
}

#define CP16(dst, src) \
    asm volatile("cp.async.cg.shared.global [%0], [%1], 16;" :: "r"(dst), "l"(src))
#define CP_COMMIT() asm volatile("cp.async.commit_group;" ::: "memory")
#define CP_WAIT1()  asm volatile("cp.async.wait_group 1;" ::: "memory")

#define LDSM4(r, addr) \
    asm volatile("ldmatrix.sync.aligned.m8n8.x4.shared.b16 {%0,%1,%2,%3}, [%4];" \
        : "=r"((r)[0]), "=r"((r)[1]), "=r"((r)[2]), "=r"((r)[3]) : "r"(addr))
#define LDSM2(r, addr) \
    asm volatile("ldmatrix.sync.aligned.m8n8.x2.shared.b16 {%0,%1}, [%2];" \
        : "=r"((r)[0]), "=r"((r)[1]) : "r"(addr))

#define MMA(c, a, b) \
    asm volatile("mma.sync.aligned.m16n8k16.row.col.f32.f16.f16.f32 " \
        "{%0,%1,%2,%3},{%4,%5,%6,%7},{%8,%9},{%0,%1,%2,%3};" \
        : "+f"((c)[0]), "+f"((c)[1]), "+f"((c)[2]), "+f"((c)[3]) \
        : "r"((a)[0]), "r"((a)[1]), "r"((a)[2]), "r"((a)[3]), "r"((b)[0]), "r"((b)[1]))

// ------------------------------- scratch ----------------------------------
__device__ __half g_xhi[MTOT*Dm],    g_xlo[MTOT*Dm];
__device__ __half g_Wqkvh[3*Dm*Dm],  g_Wqkvl[3*Dm*Dm];
__device__ __half g_Woh[Dm*Dm],      g_Wol[Dm*Dm];
__device__ __half g_W1h[FFNm*Dm],    g_W1l[FFNm*Dm];
__device__ __half g_W2h[Dm*FFNm],    g_W2l[Dm*FFNm];
__device__ __half g_qh[Bb*Hh*Ss*HD], g_ql[Bb*Hh*Ss*HD];
__device__ __half g_kh[Bb*Hh*Ss*HD], g_kl[Bb*Hh*Ss*HD];
__device__ __half g_vth[Bb*Hh*Ss*HD], g_vtl[Bb*Hh*Ss*HD];   // [z][d][s]
__device__ __half g_ctxh[MTOT*Dm],   g_ctxl[MTOT*Dm];
__device__ float  g_r1[MTOT*Dm];
__device__ float  g_h[MTOT*Dm];
__device__ __half g_hh[MTOT*Dm],     g_hl[MTOT*Dm];
__device__ __half g_f1h[(size_t)MTOT*FFNm], g_f1l[(size_t)MTOT*FFNm];
__device__ float  g_r2[MTOT*Dm];

// ------------------------------- split utils ------------------------------
__device__ __forceinline__ void splitpair(float a, float b, uint32_t& h, uint32_t& l) {
    __half ha = __float2half_rn(a), hb = __float2half_rn(b);
    __half la = __float2half_rn(a - __half2float(ha));
    __half lb = __float2half_rn(b - __half2float(hb));
    h = (uint32_t)__half_as_ushort(ha) | ((uint32_t)__half_as_ushort(hb) << 16);
    l = (uint32_t)__half_as_ushort(la) | ((uint32_t)__half_as_ushort(lb) << 16);
}

// ------------------------------- GEMM (HMMA) -------------------------------
// C[M,N] = A[M,K] @ B[N,K]^T, split-fp16 operands, fp32 accumulators.
// BM=128, BK=32, 256 threads = 8 warps (2 Mwarps x 4 Nwarps).
// MODE 0: qkv scatter; MODE 3/5: +bias+resid; MODE 4: relu+bias -> split.
template<int BN, int MODE>
__global__ __launch_bounds__(256)
void mma_gemm(const __half* __restrict__ Ahi, const __half* __restrict__ Alo,
              const __half* __restrict__ Bhi, const __half* __restrict__ Blo,
              const float* __restrict__ bias, int K, long sA, long sB,
              const float* __restrict__ resid,
              int Nc, float* __restrict__ Cf,
              __half* __restrict__ Chi, __half* __restrict__ Clo,
              __half* __restrict__ qh, __half* __restrict__ ql,
              __half* __restrict__ kh, __half* __restrict__ kl,
              __half* __restrict__ vh, __half* __restrict__ vl)
{
    constexpr int A_BYTES = 128 * 80;
    constexpr int B_BYTES = BN * 80;
    constexpr int STAGE   = 2 * A_BYTES + 2 * B_BYTES;
    constexpr int WN = BN / 4;
    constexpr int NT = WN / 8;

    const int tid = threadIdx.x;
    const int wid = tid >> 5, l = tid & 31;
    const int wm = wid >> 2, wn = wid & 3;
    const int z  = blockIdx.z;
    const int m0 = blockIdx.y * 128;
    const int n0 = blockIdx.x * BN;

    const __half *pAh = Ahi + (size_t)z * sA, *pAl = Alo + (size_t)z * sA;
    const __half *pBh = Bhi + (size_t)z * sB, *pBl = Blo + (size_t)z * sB;

    extern __shared__ char dsm[];
    const uint32_t smem_base = smem_u32(dsm);

    uint32_t aoff[4];
    #pragma unroll
    for (int mt = 0; mt < 4; mt++)
        aoff[mt] = (uint32_t)((wm*64 + mt*16 + (l & 15)) * 80 + (l >> 4) * 16);
    uint32_t boff[NT];
    #pragma unroll
    for (int nt = 0; nt < NT; nt++)
        boff[nt] = (uint32_t)((wn*WN + nt*8 + (l & 7)) * 80 + ((l >> 3) & 1) * 16);

    float acc[4][NT][4];
    #pragma unroll
    for (int mt = 0; mt < 4; mt++)
        #pragma unroll
        for (int nt = 0; nt < NT; nt++)
            #pragma unroll
            for (int j = 0; j < 4; j++) acc[mt][nt][j] = 0.f;

    const int niter = K >> 5;

    auto load_stage = [&](int st, int k0) {
        uint32_t base = smem_base + st * STAGE;
        #pragma unroll
        for (int i = 0; i < 2; i++) {
            int id = tid + (i << 8);
            int r = id >> 2, c = id & 3;
            size_t g = (size_t)(m0 + r) * K + k0 + c * 8;
            uint32_t d = base + r * 80 + c * 16;
            CP16(d, pAh + g);
            CP16(d + A_BYTES, pAl + g);
        }
        #pragma unroll
        for (int i = 0; i < BN / 64; i++) {
            int id = tid + (i << 8);
            int r = id >> 2, c = id & 3;
            size_t g = (size_t)(n0 + r) * K + k0 + c * 8;
            uint32_t d = base + 2 * A_BYTES + r * 80 + c * 16;
            CP16(d, pBh + g);
            CP16(d + B_BYTES, pBl + g);
        }
    };

    load_stage(0, 0);  CP_COMMIT();
    if (niter > 1) load_stage(1, 32);
    CP_COMMIT();

    for (int it = 0; it < niter; it++) {
        CP_WAIT1();
        __syncthreads();

        int pf = it + 2;
        if (pf < niter) load_stage(pf % 3, pf << 5);
        CP_COMMIT();

        const uint32_t sAb = smem_base + (it % 3) * STAGE;
        const uint32_t sBb = sAb + 2 * A_BYTES;
        #pragma unroll
        for (int ks = 0; ks < 2; ks++) {
            uint32_t ah[4][4], al[4][4];
            #pragma unroll
            for (int mt = 0; mt < 4; mt++) {
                uint32_t addr = sAb + aoff[mt] + ks * 32;
                LDSM4(ah[mt], addr);
                LDSM4(al[mt], addr + A_BYTES);
            }
            #pragma unroll
            for (int nt = 0; nt < NT; nt++) {
                uint32_t bh[2], bl[2];
                uint32_t baddr = sBb + boff[nt] + ks * 32;
                LDSM2(bh, baddr);
                LDSM2(bl, baddr + B_BYTES);
                #pragma unroll
                for (int mt = 0; mt < 4; mt++) {
                    MMA(acc[mt][nt], ah[mt], bh);
                    MMA(acc[mt][nt], ah[mt], bl);
                    MMA(acc[mt][nt], al[mt], bh);
                }
            }
        }
    }

    const int rbase = m0 + wm*64 + (l >> 2);
    const int cbase = n0 + wn*WN + 2*(l & 3);

    #pragma unroll
    for (int mt = 0; mt < 4; mt++) {
        #pragma unroll
        for (int nt = 0; nt < NT; nt++) {
            const int col = cbase + nt*8;
            #pragma unroll
            for (int half_ : {0, 1}) {
                const int row = rbase + mt*16 + half_*8;
                float v0 = acc[mt][nt][half_*2 + 0];
                float v1 = acc[mt][nt][half_*2 + 1];

                if (MODE == 0) {
                    float f0 = v0 + bias[col], f1 = v1 + bias[col + 1];
                    const int which = col >> 10;
                    const int hm = col & 1023;
                    const int hidx = hm >> 6, d = hm & 63;
                    const int b = row >> 10, s = row & 1023;
                    const int zz = (b << 4) + hidx;
                    if (which == 0) { f0 *= 0.125f; f1 *= 0.125f; }
                    if (which < 2) {
                        __half* th = (which == 0) ? qh : kh;
                        __half* tl = (which == 0) ? ql : kl;
                        size_t idx = ((size_t)zz * Ss + s) * 64 + d;
                        uint32_t hv, lv;
                        splitpair(f0, f1, hv, lv);
                        *(uint32_t*)(th + idx) = hv;
                        *(uint32_t*)(tl + idx) = lv;
                    } else {
                        size_t i0 = ((size_t)zz * 64 + d) * Ss + s;
                        __half h0 = __float2half_rn(f0), h1 = __float2half_rn(f1);
                        vh[i0] = h0;
                        vh[i0 + Ss] = h1;
                        vl[i0] = __float2half_rn(f0 - __half2float(h0));
                        vl[i0 + Ss] = __float2half_rn(f1 - __half2float(h1));
                    }
                } else if (MODE == 3 || MODE == 5) {
                    size_t idx = (size_t)row * Nc + col;
                    float2 rv = *(const float2*)(resid + idx);
                    float2 o;
                    o.x = v0 + bias[col]     + rv.x;
                    o.y = v1 + bias[col + 1] + rv.y;
                    *(float2*)(Cf + idx) = o;
                } else { // MODE 4
                    size_t idx = (size_t)row * Nc + col;
                    float f0 = fmaxf(v0 + bias[col], 0.f);
                    float f1 = fmaxf(v1 + bias[col + 1], 0.f);
                    uint32_t hv, lv;
                    splitpair(f0, f1, hv, lv);
                    *(uint32_t*)(Chi + idx) = hv;
                    *(uint32_t*)(Clo + idx) = lv;
                }
            }
        }
    }
}

// --------------------------- flash attention -------------------------------
// One CTA per (z, 128-query block). 8 warps, each owns 16 query rows.
// S = Q@K^T (3-term split MMA, q pre-scaled), key mask, online softmax,
// O += P@V^T (3-term, P split in registers), final 1/lsum + split-write ctx.
// Q tile + register Q-fragments resident; K/V double-buffered via cp.async.
__global__ __launch_bounds__(256)
void flash_attn(const __half* __restrict__ qh_, const __half* __restrict__ ql_,
                const __half* __restrict__ kh_, const __half* __restrict__ kl_,
                const __half* __restrict__ vh_, const __half* __restrict__ vl_,
                const int* __restrict__ mask,
                __half* __restrict__ cxh, __half* __restrict__ cxl)
{
    constexpr int QSTRIDE = 144;             // 64 halves + 8 pad (9 chunks, odd)
    constexpr int QTILE   = 128 * QSTRIDE;   // 18432 B
    constexpr int VSTRIDE = 272;             // 128 halves + 8 pad (17 chunks, odd)
    constexpr int VTILE   = 64 * VSTRIDE;    // 17408 B
    constexpr int NBLK    = Ss / 128;        // 8 key blocks

    const int z  = blockIdx.y;               // b*16 + h
    const int q0 = blockIdx.x * 128;
    const int b  = z >> 4, h = z & 15;
    const int tid = threadIdx.x, wid = tid >> 5, l = tid & 31;

    extern __shared__ char sm[];
    const uint32_t base = smem_u32(sm);
    const uint32_t sQh = base;
    const uint32_t sQl = sQh + QTILE;
    const uint32_t sKh = sQl + QTILE;        // [2 stages]
    const uint32_t sKl = sKh + 2 * QTILE;
    const uint32_t sVh = sKl + 2 * QTILE;    // [2 stages]
    const uint32_t sVl = sVh + 2 * VTILE;
    int* sMask = (int*)(sm + (sVl - base) + 2 * VTILE);   // [2][128]

    const __half* qhz = qh_ + (size_t)z * Ss * 64;
    const __half* qlz = ql_ + (size_t)z * Ss * 64;
    const __half* khz = kh_ + (size_t)z * Ss * 64;
    const __half* klz = kl_ + (size_t)z * Ss * 64;
    const __half* vhz = vh_ + (size_t)z * 64 * Ss;
    const __half* vlz = vl_ + (size_t)z * 64 * Ss;
    const int*    mz  = mask + (size_t)z * Ss;

    auto load_q = [&]() {
        #pragma unroll
        for (int i = 0; i < 4; i++) {
            int id = tid + (i << 8);
            int r = id >> 3, c = id & 7;
            size_t g = (size_t)(q0 + r) * 64 + c * 8;
            uint32_t d = r * QSTRIDE + c * 16;
            CP16(sQh + d, qhz + g);
            CP16(sQl + d, qlz + g);
        }
    };
    auto load_kv = [&](int blk, int st) {
        int key0 = blk * 128;
        #pragma unroll
        for (int i = 0; i < 4; i++) {        // K: 128 rows x 8 chunks
            int id = tid + (i << 8);
            int r = id >> 3, c = id & 7;
            size_t g = (size_t)(key0 + r) * 64 + c * 8;
            uint32_t d = st * QTILE + r * QSTRIDE + c * 16;
            CP16(sKh + d, khz + g);
            CP16(sKl + d, klz + g);
        }
        #pragma unroll
        for (int i = 0; i < 4; i++) {        // V: 64 rows x 16 chunks
            int id = tid + (i << 8);
            int r = id >> 4, c = id & 15;
            size_t g = (size_t)r * Ss + key0 + c * 8;
            uint32_t d = st * VTILE + r * VSTRIDE + c * 16;
            CP16(sVh + d, vhz + g);
            CP16(sVl + d, vlz + g);
        }
        if (tid < 128) sMask[st * 128 + tid] = mz[key0 + tid];
    };

    // prologue
    load_q();
    load_kv(0, 0);
    CP_COMMIT();
    load_kv(1, 1);
    CP_COMMIT();

    uint32_t qfh[4][4], qfl[4][4];
    float o[8][4];
    #pragma unroll
    for (int nt = 0; nt < 8; nt++)
        #pragma unroll
        for (int j = 0; j < 4; j++) o[nt][j] = 0.f;
    float mA = -1e30f, mB = -1e30f, lsA = 0.f, lsB = 0.f;

    const uint32_t qrow = (uint32_t)((wid*16 + (l & 15)) * QSTRIDE + (l >> 4) * 16);
    const uint32_t krow = (uint32_t)(((l & 7)) * QSTRIDE + ((l >> 3) & 1) * 16);
    const uint32_t vrow = (uint32_t)(((l & 7)) * VSTRIDE + ((l >> 3) & 1) * 16);

    for (int it = 0; it < NBLK; it++) {
        CP_WAIT1();
        __syncthreads();

        if (it == 0) {
            #pragma unroll
            for (int ks = 0; ks < 4; ks++) {
                LDSM4(qfh[ks], sQh + qrow + ks * 32);
                LDSM4(qfl[ks], sQl + qrow + ks * 32);
            }
        }

        const int st = it & 1;
        const uint32_t kb = sKh + st * QTILE;
        const uint32_t lb = sKl + st * QTILE;

        // ---- S = Q K^T (16 rows x 128 keys per warp) ----
        float s[16][4];
        #pragma unroll
        for (int nt = 0; nt < 16; nt++)
            #pragma unroll
            for (int j = 0; j < 4; j++) s[nt][j] = 0.f;

        #pragma unroll
        for (int ks = 0; ks < 4; ks++) {
            #pragma unroll
            for (int nt = 0; nt < 16; nt++) {
                uint32_t bh[2], bl2[2];
                uint32_t addr = krow + nt * 8 * QSTRIDE + ks * 32;
                LDSM2(bh,  kb + addr);
                LDSM2(bl2, lb + addr);
                MMA(s[nt], qfh[ks], bh);
                MMA(s[nt], qfh[ks], bl2);
                MMA(s[nt], qfl[ks], bh);
            }
        }

        // ---- mask + online softmax ----
        const int* mk = sMask + st * 128;
        float mxA = -1e30f, mxB = -1e30f;
        #pragma unroll
        for (int nt = 0; nt < 16; nt++) {
            int c0 = nt*8 + (l & 3)*2;
            if (!mk[c0])     { s[nt][0] = NEGV; s[nt][2] = NEGV; }
            if (!mk[c0 + 1]) { s[nt][1] = NEGV; s[nt][3] = NEGV; }
            mxA = fmaxf(mxA, fmaxf(s[nt][0], s[nt][1]));
            mxB = fmaxf(mxB, fmaxf(s[nt][2], s[nt][3]));
        }
        mxA = fmaxf(mxA, __shfl_xor_sync(0xffffffffu, mxA, 1));
        mxA = fmaxf(mxA, __shfl_xor_sync(0xffffffffu, mxA, 2));
        mxB = fmaxf(mxB, __shfl_xor_sync(0xffffffffu, mxB, 1));
        mxB = fmaxf(mxB, __shfl_xor_sync(0xffffffffu, mxB, 2));

        float mAn = fmaxf(mA, mxA), mBn = fmaxf(mB, mxB);
        float scA = __expf(mA - mAn), scB = __expf(mB - mBn);
        mA = mAn; mB = mBn;

        float sumA = 0.f, sumB = 0.f;
        #pragma unroll
        for (int nt = 0; nt < 16; nt++) {
            s[nt][0] = __expf(s[nt][0] - mAn);
            s[nt][1] = __expf(s[nt][1] - mAn);
            s[nt][2] = __expf(s[nt][2] - mBn);
            s[nt][3] = __expf(s[nt][3] - mBn);
            sumA += s[nt][0] + s[nt][1];
            sumB += s[nt][2] + s[nt][3];
        }
        sumA += __shfl_xor_sync(0xffffffffu, sumA, 1);
        sumA += __shfl_xor_sync(0xffffffffu, sumA, 2);
        sumB += __shfl_xor_sync(0xffffffffu, sumB, 1);
        sumB += __shfl_xor_sync(0xffffffffu, sumB, 2);
        lsA = lsA * scA + sumA;
        lsB = lsB * scB + sumB;

        #pragma unroll
        for (int nt = 0; nt < 8; nt++) {
            o[nt][0] *= scA; o[nt][1] *= scA;
            o[nt][2] *= scB; o[nt][3] *= scB;
        }

        // ---- O += P V^T (P in registers, split hi/lo) ----
        const uint32_t vb  = sVh + st * VTILE;
        const uint32_t vlb = sVl + st * VTILE;
        #pragma unroll
        for (int ks = 0; ks < 8; ks++) {
            uint32_t ah[4], al[4];
            splitpair(s[2*ks][0],   s[2*ks][1],   ah[0], al[0]);
            splitpair(s[2*ks][2],   s[2*ks][3],   ah[1], al[1]);
            splitpair(s[2*ks+1][0], s[2*ks+1][1], ah[2], al[2]);
            splitpair(s[2*ks+1][2], s[2*ks+1][3], ah[3], al[3]);
            #pragma unroll
            for (int nt = 0; nt < 8; nt++) {
                uint32_t vh2[2], vl2[2];
                uint32_t addr = vrow + nt * 8 * VSTRIDE + ks * 32;
                LDSM2(vh2, vb  + addr);
                LDSM2(vl2, vlb + addr);
                MMA(o[nt], ah, vh2);
                MMA(o[nt], al, vh2);
                MMA(o[nt], ah, vl2);
            }
        }

        __syncthreads();
        if (it + 2 < NBLK) load_kv(it + 2, st);
        CP_COMMIT();
    }

    // ---- epilogue: scale by 1/lsum, split-write ctx[b, s, h*64+d] ----
    const float invA = 1.f / lsA, invB = 1.f / lsB;
    const int rowA = (b << 10) + q0 + wid*16 + (l >> 2);
    const int rowB = rowA + 8;
    #pragma unroll
    for (int nt = 0; nt < 8; nt++) {
        const int col = (h << 6) + nt*8 + (l & 3)*2;
        uint32_t hv, lv;
        splitpair(o[nt][0] * invA, o[nt][1] * invA, hv, lv);
        *(uint32_t*)(cxh + (size_t)rowA * Dm + col) = hv;
        *(uint32_t*)(cxl + (size_t)rowA * Dm + col) = lv;
        splitpair(o[nt][2] * invB, o[nt][3] * invB, hv, lv);
        *(uint32_t*)(cxh + (size_t)rowB * Dm + col) = hv;
        *(uint32_t*)(cxl + (size_t)rowB * Dm + col) = lv;
    }
}

// ------------------------------- aux kernels -------------------------------
__global__ __launch_bounds__(256)
void split_k(const float* __restrict__ in, __half* __restrict__ hi,
             __half* __restrict__ lo, int n4)
{
    int i = blockIdx.x * 256 + threadIdx.x;
    if (i >= n4) return;
    float4 v = ((const float4*)in)[i];
    uint2 hv, lv;
    splitpair(v.x, v.y, hv.x, lv.x);
    splitpair(v.z, v.w, hv.y, lv.y);
    ((uint2*)hi)[i] = hv;
    ((uint2*)lo)[i] = lv;
}

__device__ __forceinline__ float blockReduceSum(float v, float* sh) {
    __syncthreads();
    int lane = threadIdx.x & 31, w = threadIdx.x >> 5;
    #pragma unroll
    for (int o = 16; o; o >>= 1) v += __shfl_xor_sync(0xffffffffu, v, o);
    if (lane == 0) sh[w] = v;
    __syncthreads();
    if (threadIdx.x == 0) {
        float s = 0.f;
        #pragma unroll
        for (int i = 0; i < 8; i++) s += sh[i];
        sh[0] = s;
    }
    __syncthreads();
    return sh[0];
}

// LayerNorm (biased variance); optionally emits split halves too
template<bool SPLIT>
__global__ __launch_bounds__(256)
void layernorm_k(const float* __restrict__ in, const float* __restrict__ g,
                 const float* __restrict__ be, float* __restrict__ out,
                 __half* __restrict__ ohi, __half* __restrict__ olo)
{
    size_t row = blockIdx.x;
    const float4* p = (const float4*)(in + row * Dm);
    int t = threadIdx.x;
    __shared__ float sh[8];

    float4 v = p[t];
    float s  = v.x + v.y + v.z + v.w;
    float sq = v.x*v.x + v.y*v.y + v.z*v.z + v.w*v.w;
    s  = blockReduceSum(s, sh);
    sq = blockReduceSum(sq, sh);
    float mean = s * (1.f / Dm);
    float var  = sq * (1.f / Dm) - mean * mean;
    float inv  = rsqrtf(var + EPSV);

    float4 gg = ((const float4*)g)[t];
    float4 bb = ((const float4*)be)[t];
    float4 o;
    o.x = gg.x * (v.x - mean) * inv + bb.x;
    o.y = gg.y * (v.y - mean) * inv + bb.y;
    o.z = gg.z * (v.z - mean) * inv + bb.z;
    o.w = gg.w * (v.w - mean) * inv + bb.w;
    ((float4*)(out + row * Dm))[t] = o;
    if (SPLIT) {
        uint2 hv, lv;
        splitpair(o.x, o.y, hv.x, lv.x);
        splitpair(o.z, o.w, hv.y, lv.y);
        ((uint2*)(ohi + row * Dm))[t] = hv;
        ((uint2*)(olo + row * Dm))[t] = lv;
    }
}

// ------------------------------- launcher ----------------------------------
static void* symaddr(const void* sym) {
    void* p = nullptr;
    cudaGetSymbolAddress(&p, sym);
    return p;
}

extern "C" void kernel_launch(void* const* d_in, const int* in_sizes, int n_in,
                              void* d_out, int out_size)
{
    const float* x    = (const float*)d_in[0];
    const int*   mask = (const int*)  d_in[1];
    const float* Wqkv = (const float*)d_in[2];
    const float* bqkv = (const float*)d_in[3];
    const float* Wo   = (const float*)d_in[4];
    const float* bo   = (const float*)d_in[5];
    const float* W1   = (const float*)d_in[6];
    const float* b1   = (const float*)d_in[7];
    const float* W2   = (const float*)d_in[8];
    const float* b2   = (const float*)d_in[9];
    const float* g1   = (const float*)d_in[10];
    const float* be1  = (const float*)d_in[11];
    const float* g2   = (const float*)d_in[12];
    const float* be2  = (const float*)d_in[13];
    float* out = (float*)d_out;

    __half* xhi = (__half*)symaddr(g_xhi);
    __half* xlo = (__half*)symaddr(g_xlo);
    __half* Wqh = (__half*)symaddr(g_Wqkvh);
    __half* Wql = (__half*)symaddr(g_Wqkvl);
    __half* Woh = (__half*)symaddr(g_Woh);
    __half* Wol = (__half*)symaddr(g_Wol);
    __half* W1h = (__half*)symaddr(g_W1h);
    __half* W1l = (__half*)symaddr(g_W1l);
    __half* W2h = (__half*)symaddr(g_W2h);
    __half* W2l = (__half*)symaddr(g_W2l);
    __half* qh  = (__half*)symaddr(g_qh);
    __half* ql  = (__half*)symaddr(g_ql);
    __half* kh  = (__half*)symaddr(g_kh);
    __half* kl  = (__half*)symaddr(g_kl);
    __half* vth = (__half*)symaddr(g_vth);
    __half* vtl = (__half*)symaddr(g_vtl);
    __half* cxh = (__half*)symaddr(g_ctxh);
    __half* cxl = (__half*)symaddr(g_ctxl);
    float*  r1  = (float*) symaddr(g_r1);
    float*  hbf = (float*) symaddr(g_h);
    __half* hhi = (__half*)symaddr(g_hh);
    __half* hlo = (__half*)symaddr(g_hl);
    __half* f1h = (__half*)symaddr(g_f1h);
    __half* f1l = (__half*)symaddr(g_f1l);
    float*  r2  = (float*) symaddr(g_r2);

    constexpr int SM128 = 3 * (2*128*80 + 2*128*80);   // 122880
    // flash: Q(2x18432) + K(4x18432) + V(4x17408) + mask(1024)
    constexpr int SMFA  = 2*18432 + 4*18432 + 4*17408 + 1024;  // 181248
    cudaFuncSetAttribute(mma_gemm<128,0>, cudaFuncAttributeMaxDynamicSharedMemorySize, SM128);
    cudaFuncSetAttribute(mma_gemm<128,3>, cudaFuncAttributeMaxDynamicSharedMemorySize, SM128);
    cudaFuncSetAttribute(mma_gemm<128,4>, cudaFuncAttributeMaxDynamicSharedMemorySize, SM128);
    cudaFuncSetAttribute(mma_gemm<128,5>, cudaFuncAttributeMaxDynamicSharedMemorySize, SM128);
    cudaFuncSetAttribute(flash_attn,      cudaFuncAttributeMaxDynamicSharedMemorySize, SMFA);

    // 0) split inputs + weights to fp16 hi/lo
    split_k<<<(MTOT*Dm/4 + 255)/256, 256>>>(x,    xhi, xlo, MTOT*Dm/4);
    split_k<<<(3*Dm*Dm/4 + 255)/256, 256>>>(Wqkv, Wqh, Wql, 3*Dm*Dm/4);
    split_k<<<(Dm*Dm/4   + 255)/256, 256>>>(Wo,   Woh, Wol, Dm*Dm/4);
    split_k<<<(FFNm*Dm/4 + 255)/256, 256>>>(W1,   W1h, W1l, FFNm*Dm/4);
    split_k<<<(Dm*FFNm/4 + 255)/256, 256>>>(W2,   W2h, W2l, Dm*FFNm/4);

    // 1) QKV projection -> scatter split q (scaled) / k / v (transposed)
    mma_gemm<128,0><<<dim3(24, 32, 1), 256, SM128>>>(
        xhi, xlo, Wqh, Wql, bqkv, Dm, 0, 0,
        nullptr, 3*Dm, nullptr, nullptr, nullptr,
        qh, ql, kh, kl, vth, vtl);

    // 2-4) fused flash attention -> split ctx
    flash_attn<<<dim3(8, 64), 256, SMFA>>>(
        qh, ql, kh, kl, vth, vtl, mask, cxh, cxl);

    // 5) out proj + residual(x)
    mma_gemm<128,3><<<dim3(8, 32, 1), 256, SM128>>>(
        cxh, cxl, Woh, Wol, bo, Dm, 0, 0,
        x, Dm, r1, nullptr, nullptr,
        nullptr, nullptr, nullptr, nullptr, nullptr, nullptr);

    // 6) LN1 (+ split h)
    layernorm_k<true><<<MTOT, 256>>>(r1, g1, be1, hbf, hhi, hlo);

    // 7) FFN1 + relu -> split f1
    mma_gemm<128,4><<<dim3(32, 32, 1), 256, SM128>>>(
        hhi, hlo, W1h, W1l, b1, Dm, 0, 0,
        nullptr, FFNm, nullptr, f1h, f1l,
        nullptr, nullptr, nullptr, nullptr, nullptr, nullptr);

    // 8) FFN2 + residual(h)
    mma_gemm<128,5><<<dim3(8, 32, 1), 256, SM128>>>(
        f1h, f1l, W2h, W2l, b2, FFNm, 0, 0,
        hbf, Dm, r2, nullptr, nullptr,
        nullptr, nullptr, nullptr, nullptr, nullptr, nullptr);

    // 9) LN2 -> output
    layernorm_k<false><<<MTOT, 256>>>(r2, g2, be2, out, nullptr, nullptr);
}

// round 5
// speedup vs baseline: 3.7526x; 1.4884x over previous
#include <cuda_runtime.h>
#include <cuda_fp16.h>
#include <cstdint>

// ---------------------------------------------------------------------------
// EncoderLayer via legacy tensor cores (mma.sync m16n8k16 fp16, f32 acc).
// Round 5: 2-term split — A operands exact (hi+lo fp16 pair), B operands
// plain fp16 (weights / K / V). C = Ahi*B + Alo*B == A_fp32 * B_fp16.
// B=4, S=1024, D=1024, H=16, hd=64, FFN=4096.
// ---------------------------------------------------------------------------

#define Dm   1024
#define Hh   16
#define HD   64
#define FFNm 4096
#define Bb   4
#define Ss   1024
#define MTOT (Bb*Ss)
#define NEGV (-1e9f)
#define EPSV (1e-12f)

// ------------------------------ ptx helpers -------------------------------
__device__ __forceinline__ uint32_t smem_u32(const void* p) {
    uint32_t a;
    asm("{ .reg .u64 t; cvta.to.shared.u64 t, %1; cvt.u32.u64 %0, t; }"
        : "=r"(a) : "l"(p));
    return a;
}

#define CP16(dst, src) \
    asm volatile("cp.async.cg.shared.global [%0], [%1], 16;" :: "r"(dst), "l"(src))
#define CP_COMMIT() asm volatile("cp.async.commit_group;" ::: "memory")
#define CP_WAIT1()  asm volatile("cp.async.wait_group 1;" ::: "memory")

#define LDSM4(r, addr) \
    asm volatile("ldmatrix.sync.aligned.m8n8.x4.shared.b16 {%0,%1,%2,%3}, [%4];" \
        : "=r"((r)[0]), "=r"((r)[1]), "=r"((r)[2]), "=r"((r)[3]) : "r"(addr))
#define LDSM2(r, addr) \
    asm volatile("ldmatrix.sync.aligned.m8n8.x2.shared.b16 {%0,%1}, [%2];" \
        : "=r"((r)[0]), "=r"((r)[1]) : "r"(addr))

#define MMA(c, a, b) \
    asm volatile("mma.sync.aligned.m16n8k16.row.col.f32.f16.f16.f32 " \
        "{%0,%1,%2,%3},{%4,%5,%6,%7},{%8,%9},{%0,%1,%2,%3};" \
        : "+f"((c)[0]), "+f"((c)[1]), "+f"((c)[2]), "+f"((c)[3]) \
        : "r"((a)[0]), "r"((a)[1]), "r"((a)[2]), "r"((a)[3]), "r"((b)[0]), "r"((b)[1]))

// ------------------------------- scratch ----------------------------------
__device__ __half g_xhi[MTOT*Dm],    g_xlo[MTOT*Dm];
__device__ __half g_Wqkvh[3*Dm*Dm];
__device__ __half g_Woh[Dm*Dm];
__device__ __half g_W1h[FFNm*Dm];
__device__ __half g_W2h[Dm*FFNm];
__device__ __half g_qh[Bb*Hh*Ss*HD], g_ql[Bb*Hh*Ss*HD];
__device__ __half g_kh[Bb*Hh*Ss*HD];
__device__ __half g_vth[Bb*Hh*Ss*HD];                       // [z][d][s]
__device__ __half g_ctxh[MTOT*Dm],   g_ctxl[MTOT*Dm];
__device__ float  g_r1[MTOT*Dm];
__device__ float  g_h[MTOT*Dm];
__device__ __half g_hh[MTOT*Dm],     g_hl[MTOT*Dm];
__device__ __half g_f1h[(size_t)MTOT*FFNm], g_f1l[(size_t)MTOT*FFNm];
__device__ float  g_r2[MTOT*Dm];

// ------------------------------- split utils ------------------------------
__device__ __forceinline__ void splitpair(float a, float b, uint32_t& h, uint32_t& l) {
    __half ha = __float2half_rn(a), hb = __float2half_rn(b);
    __half la = __float2half_rn(a - __half2float(ha));
    __half lb = __float2half_rn(b - __half2float(hb));
    h = (uint32_t)__half_as_ushort(ha) | ((uint32_t)__half_as_ushort(hb) << 16);
    l = (uint32_t)__half_as_ushort(la) | ((uint32_t)__half_as_ushort(lb) << 16);
}
__device__ __forceinline__ uint32_t packpair(float a, float b) {
    __half ha = __float2half_rn(a), hb = __float2half_rn(b);
    return (uint32_t)__half_as_ushort(ha) | ((uint32_t)__half_as_ushort(hb) << 16);
}

// ------------------------------- GEMM (HMMA) -------------------------------
// C[M,N] = A[M,K] @ B[N,K]^T; A split hi/lo (2 MMA terms), B plain fp16.
// BM=128, BK=32, 256 threads = 8 warps (2 Mwarps x 4 Nwarps).
// MODE 0: qkv scatter (q scaled+split, k fp16, v fp16 transposed)
// MODE 3/5: +bias+resid -> fp32
// MODE 4: relu+bias -> split halves
template<int BN, int MODE>
__global__ __launch_bounds__(256)
void mma_gemm(const __half* __restrict__ Ahi, const __half* __restrict__ Alo,
              const __half* __restrict__ Bhi,
              const float* __restrict__ bias, int K,
              const float* __restrict__ resid,
              int Nc, float* __restrict__ Cf,
              __half* __restrict__ Chi, __half* __restrict__ Clo,
              __half* __restrict__ qh, __half* __restrict__ ql,
              __half* __restrict__ kh, __half* __restrict__ vh)
{
    constexpr int A_BYTES = 128 * 80;
    constexpr int B_BYTES = BN * 80;
    constexpr int STAGE   = 2 * A_BYTES + B_BYTES;
    constexpr int WN = BN / 4;
    constexpr int NT = WN / 8;

    const int tid = threadIdx.x;
    const int wid = tid >> 5, l = tid & 31;
    const int wm = wid >> 2, wn = wid & 3;
    const int m0 = blockIdx.y * 128;
    const int n0 = blockIdx.x * BN;

    extern __shared__ char dsm[];
    const uint32_t smem_base = smem_u32(dsm);

    uint32_t aoff[4];
    #pragma unroll
    for (int mt = 0; mt < 4; mt++)
        aoff[mt] = (uint32_t)((wm*64 + mt*16 + (l & 15)) * 80 + (l >> 4) * 16);
    uint32_t boff[NT];
    #pragma unroll
    for (int nt = 0; nt < NT; nt++)
        boff[nt] = (uint32_t)((wn*WN + nt*8 + (l & 7)) * 80 + ((l >> 3) & 1) * 16);

    float acc[4][NT][4];
    #pragma unroll
    for (int mt = 0; mt < 4; mt++)
        #pragma unroll
        for (int nt = 0; nt < NT; nt++)
            #pragma unroll
            for (int j = 0; j < 4; j++) acc[mt][nt][j] = 0.f;

    const int niter = K >> 5;

    auto load_stage = [&](int st, int k0) {
        uint32_t base = smem_base + st * STAGE;
        #pragma unroll
        for (int i = 0; i < 2; i++) {
            int id = tid + (i << 8);
            int r = id >> 2, c = id & 3;
            size_t g = (size_t)(m0 + r) * K + k0 + c * 8;
            uint32_t d = base + r * 80 + c * 16;
            CP16(d, Ahi + g);
            CP16(d + A_BYTES, Alo + g);
        }
        #pragma unroll
        for (int i = 0; i < BN / 64; i++) {
            int id = tid + (i << 8);
            int r = id >> 2, c = id & 3;
            size_t g = (size_t)(n0 + r) * K + k0 + c * 8;
            CP16(base + 2 * A_BYTES + r * 80 + c * 16, Bhi + g);
        }
    };

    load_stage(0, 0);  CP_COMMIT();
    if (niter > 1) load_stage(1, 32);
    CP_COMMIT();

    for (int it = 0; it < niter; it++) {
        CP_WAIT1();
        __syncthreads();

        int pf = it + 2;
        if (pf < niter) load_stage(pf % 3, pf << 5);
        CP_COMMIT();

        const uint32_t sAb = smem_base + (it % 3) * STAGE;
        const uint32_t sBb = sAb + 2 * A_BYTES;
        #pragma unroll
        for (int ks = 0; ks < 2; ks++) {
            uint32_t ah[4][4], al[4][4];
            #pragma unroll
            for (int mt = 0; mt < 4; mt++) {
                uint32_t addr = sAb + aoff[mt] + ks * 32;
                LDSM4(ah[mt], addr);
                LDSM4(al[mt], addr + A_BYTES);
            }
            #pragma unroll
            for (int nt = 0; nt < NT; nt++) {
                uint32_t bh[2];
                LDSM2(bh, sBb + boff[nt] + ks * 32);
                #pragma unroll
                for (int mt = 0; mt < 4; mt++) {
                    MMA(acc[mt][nt], ah[mt], bh);
                    MMA(acc[mt][nt], al[mt], bh);
                }
            }
        }
    }

    const int rbase = m0 + wm*64 + (l >> 2);
    const int cbase = n0 + wn*WN + 2*(l & 3);

    #pragma unroll
    for (int mt = 0; mt < 4; mt++) {
        #pragma unroll
        for (int nt = 0; nt < NT; nt++) {
            const int col = cbase + nt*8;
            #pragma unroll
            for (int half_ : {0, 1}) {
                const int row = rbase + mt*16 + half_*8;
                float v0 = acc[mt][nt][half_*2 + 0];
                float v1 = acc[mt][nt][half_*2 + 1];

                if (MODE == 0) {
                    float f0 = v0 + bias[col], f1 = v1 + bias[col + 1];
                    const int which = col >> 10;
                    const int hm = col & 1023;
                    const int hidx = hm >> 6, d = hm & 63;
                    const int b = row >> 10, s = row & 1023;
                    const int zz = (b << 4) + hidx;
                    if (which == 0) {
                        f0 *= 0.125f; f1 *= 0.125f;
                        size_t idx = ((size_t)zz * Ss + s) * 64 + d;
                        uint32_t hv, lv;
                        splitpair(f0, f1, hv, lv);
                        *(uint32_t*)(qh + idx) = hv;
                        *(uint32_t*)(ql + idx) = lv;
                    } else if (which == 1) {
                        size_t idx = ((size_t)zz * Ss + s) * 64 + d;
                        *(uint32_t*)(kh + idx) = packpair(f0, f1);
                    } else {
                        size_t i0 = ((size_t)zz * 64 + d) * Ss + s;
                        vh[i0]      = __float2half_rn(f0);
                        vh[i0 + Ss] = __float2half_rn(f1);
                    }
                } else if (MODE == 3 || MODE == 5) {
                    size_t idx = (size_t)row * Nc + col;
                    float2 rv = *(const float2*)(resid + idx);
                    float2 o;
                    o.x = v0 + bias[col]     + rv.x;
                    o.y = v1 + bias[col + 1] + rv.y;
                    *(float2*)(Cf + idx) = o;
                } else { // MODE 4
                    size_t idx = (size_t)row * Nc + col;
                    float f0 = fmaxf(v0 + bias[col], 0.f);
                    float f1 = fmaxf(v1 + bias[col + 1], 0.f);
                    uint32_t hv, lv;
                    splitpair(f0, f1, hv, lv);
                    *(uint32_t*)(Chi + idx) = hv;
                    *(uint32_t*)(Clo + idx) = lv;
                }
            }
        }
    }
}

// --------------------------- flash attention -------------------------------
// One CTA per (z, 128-query block). 8 warps, each owns 16 query rows.
// S = Q@K^T (Q split 2-term, K fp16), key mask, online softmax,
// O += P@V^T (P split in registers 2-term, V fp16), final 1/lsum, split ctx.
__global__ __launch_bounds__(256)
void flash_attn(const __half* __restrict__ qh_, const __half* __restrict__ ql_,
                const __half* __restrict__ kh_, const __half* __restrict__ vh_,
                const int* __restrict__ mask,
                __half* __restrict__ cxh, __half* __restrict__ cxl)
{
    constexpr int QSTRIDE = 144;             // 64 halves + 8 pad
    constexpr int QTILE   = 128 * QSTRIDE;   // 18432 B
    constexpr int VSTRIDE = 272;             // 128 halves + 8 pad
    constexpr int VTILE   = 64 * VSTRIDE;    // 17408 B
    constexpr int NBLK    = Ss / 128;

    const int z  = blockIdx.y;               // b*16 + h
    const int q0 = blockIdx.x * 128;
    const int b  = z >> 4, h = z & 15;
    const int tid = threadIdx.x, wid = tid >> 5, l = tid & 31;

    extern __shared__ char sm[];
    const uint32_t base = smem_u32(sm);
    const uint32_t sQh = base;
    const uint32_t sQl = sQh + QTILE;
    const uint32_t sKh = sQl + QTILE;        // [2 stages]
    const uint32_t sVh = sKh + 2 * QTILE;    // [2 stages]
    int* sMask = (int*)(sm + (sVh - base) + 2 * VTILE);   // [2][128]

    const __half* qhz = qh_ + (size_t)z * Ss * 64;
    const __half* qlz = ql_ + (size_t)z * Ss * 64;
    const __half* khz = kh_ + (size_t)z * Ss * 64;
    const __half* vhz = vh_ + (size_t)z * 64 * Ss;
    const int*    mz  = mask + (size_t)z * Ss;

    auto load_q = [&]() {
        #pragma unroll
        for (int i = 0; i < 4; i++) {
            int id = tid + (i << 8);
            int r = id >> 3, c = id & 7;
            size_t g = (size_t)(q0 + r) * 64 + c * 8;
            uint32_t d = r * QSTRIDE + c * 16;
            CP16(sQh + d, qhz + g);
            CP16(sQl + d, qlz + g);
        }
    };
    auto load_kv = [&](int blk, int st) {
        int key0 = blk * 128;
        #pragma unroll
        for (int i = 0; i < 4; i++) {        // K: 128 rows x 8 chunks
            int id = tid + (i << 8);
            int r = id >> 3, c = id & 7;
            CP16(sKh + st * QTILE + r * QSTRIDE + c * 16,
                 khz + (size_t)(key0 + r) * 64 + c * 8);
        }
        #pragma unroll
        for (int i = 0; i < 4; i++) {        // V: 64 rows x 16 chunks
            int id = tid + (i << 8);
            int r = id >> 4, c = id & 15;
            CP16(sVh + st * VTILE + r * VSTRIDE + c * 16,
                 vhz + (size_t)r * Ss + key0 + c * 8);
        }
        if (tid < 128) sMask[st * 128 + tid] = mz[key0 + tid];
    };

    load_q();
    load_kv(0, 0);
    CP_COMMIT();
    load_kv(1, 1);
    CP_COMMIT();

    uint32_t qfh[4][4], qfl[4][4];
    float o[8][4];
    #pragma unroll
    for (int nt = 0; nt < 8; nt++)
        #pragma unroll
        for (int j = 0; j < 4; j++) o[nt][j] = 0.f;
    float mA = -1e30f, mB = -1e30f, lsA = 0.f, lsB = 0.f;

    const uint32_t qrow = (uint32_t)((wid*16 + (l & 15)) * QSTRIDE + (l >> 4) * 16);
    const uint32_t krow = (uint32_t)(((l & 7)) * QSTRIDE + ((l >> 3) & 1) * 16);
    const uint32_t vrow = (uint32_t)(((l & 7)) * VSTRIDE + ((l >> 3) & 1) * 16);

    for (int it = 0; it < NBLK; it++) {
        CP_WAIT1();
        __syncthreads();

        if (it == 0) {
            #pragma unroll
            for (int ks = 0; ks < 4; ks++) {
                LDSM4(qfh[ks], sQh + qrow + ks * 32);
                LDSM4(qfl[ks], sQl + qrow + ks * 32);
            }
        }

        const int st = it & 1;
        const uint32_t kb = sKh + st * QTILE;

        // ---- S = Q K^T ----
        float s[16][4];
        #pragma unroll
        for (int nt = 0; nt < 16; nt++)
            #pragma unroll
            for (int j = 0; j < 4; j++) s[nt][j] = 0.f;

        #pragma unroll
        for (int ks = 0; ks < 4; ks++) {
            #pragma unroll
            for (int nt = 0; nt < 16; nt++) {
                uint32_t bh[2];
                LDSM2(bh, kb + krow + nt * 8 * QSTRIDE + ks * 32);
                MMA(s[nt], qfh[ks], bh);
                MMA(s[nt], qfl[ks], bh);
            }
        }

        // ---- mask + online softmax ----
        const int* mk = sMask + st * 128;
        float mxA = -1e30f, mxB = -1e30f;
        #pragma unroll
        for (int nt = 0; nt < 16; nt++) {
            int c0 = nt*8 + (l & 3)*2;
            if (!mk[c0])     { s[nt][0] = NEGV; s[nt][2] = NEGV; }
            if (!mk[c0 + 1]) { s[nt][1] = NEGV; s[nt][3] = NEGV; }
            mxA = fmaxf(mxA, fmaxf(s[nt][0], s[nt][1]));
            mxB = fmaxf(mxB, fmaxf(s[nt][2], s[nt][3]));
        }
        mxA = fmaxf(mxA, __shfl_xor_sync(0xffffffffu, mxA, 1));
        mxA = fmaxf(mxA, __shfl_xor_sync(0xffffffffu, mxA, 2));
        mxB = fmaxf(mxB, __shfl_xor_sync(0xffffffffu, mxB, 1));
        mxB = fmaxf(mxB, __shfl_xor_sync(0xffffffffu, mxB, 2));

        float mAn = fmaxf(mA, mxA), mBn = fmaxf(mB, mxB);
        float scA = __expf(mA - mAn), scB = __expf(mB - mBn);
        mA = mAn; mB = mBn;

        float sumA = 0.f, sumB = 0.f;
        #pragma unroll
        for (int nt = 0; nt < 16; nt++) {
            s[nt][0] = __expf(s[nt][0] - mAn);
            s[nt][1] = __expf(s[nt][1] - mAn);
            s[nt][2] = __expf(s[nt][2] - mBn);
            s[nt][3] = __expf(s[nt][3] - mBn);
            sumA += s[nt][0] + s[nt][1];
            sumB += s[nt][2] + s[nt][3];
        }
        sumA += __shfl_xor_sync(0xffffffffu, sumA, 1);
        sumA += __shfl_xor_sync(0xffffffffu, sumA, 2);
        sumB += __shfl_xor_sync(0xffffffffu, sumB, 1);
        sumB += __shfl_xor_sync(0xffffffffu, sumB, 2);
        lsA = lsA * scA + sumA;
        lsB = lsB * scB + sumB;

        #pragma unroll
        for (int nt = 0; nt < 8; nt++) {
            o[nt][0] *= scA; o[nt][1] *= scA;
            o[nt][2] *= scB; o[nt][3] *= scB;
        }

        // ---- O += P V^T (P split hi/lo in registers, V fp16) ----
        const uint32_t vb = sVh + st * VTILE;
        #pragma unroll
        for (int ks = 0; ks < 8; ks++) {
            uint32_t ah[4], al[4];
            splitpair(s[2*ks][0],   s[2*ks][1],   ah[0], al[0]);
            splitpair(s[2*ks][2],   s[2*ks][3],   ah[1], al[1]);
            splitpair(s[2*ks+1][0], s[2*ks+1][1], ah[2], al[2]);
            splitpair(s[2*ks+1][2], s[2*ks+1][3], ah[3], al[3]);
            #pragma unroll
            for (int nt = 0; nt < 8; nt++) {
                uint32_t vh2[2];
                LDSM2(vh2, vb + vrow + nt * 8 * VSTRIDE + ks * 32);
                MMA(o[nt], ah, vh2);
                MMA(o[nt], al, vh2);
            }
        }

        __syncthreads();
        if (it + 2 < NBLK) load_kv(it + 2, st);
        CP_COMMIT();
    }

    // ---- epilogue: scale by 1/lsum, split-write ctx[b, s, h*64+d] ----
    const float invA = 1.f / lsA, invB = 1.f / lsB;
    const int rowA = (b << 10) + q0 + wid*16 + (l >> 2);
    const int rowB = rowA + 8;
    #pragma unroll
    for (int nt = 0; nt < 8; nt++) {
        const int col = (h << 6) + nt*8 + (l & 3)*2;
        uint32_t hv, lv;
        splitpair(o[nt][0] * invA, o[nt][1] * invA, hv, lv);
        *(uint32_t*)(cxh + (size_t)rowA * Dm + col) = hv;
        *(uint32_t*)(cxl + (size_t)rowA * Dm + col) = lv;
        splitpair(o[nt][2] * invB, o[nt][3] * invB, hv, lv);
        *(uint32_t*)(cxh + (size_t)rowB * Dm + col) = hv;
        *(uint32_t*)(cxl + (size_t)rowB * Dm + col) = lv;
    }
}

// ------------------------------- aux kernels -------------------------------
__global__ __launch_bounds__(256)
void split_k(const float* __restrict__ in, __half* __restrict__ hi,
             __half* __restrict__ lo, int n4)
{
    int i = blockIdx.x * 256 + threadIdx.x;
    if (i >= n4) return;
    float4 v = ((const float4*)in)[i];
    uint2 hv, lv;
    splitpair(v.x, v.y, hv.x, lv.x);
    splitpair(v.z, v.w, hv.y, lv.y);
    ((uint2*)hi)[i] = hv;
    ((uint2*)lo)[i] = lv;
}

__global__ __launch_bounds__(256)
void tohalf_k(const float* __restrict__ in, __half* __restrict__ hi, int n4)
{
    int i = blockIdx.x * 256 + threadIdx.x;
    if (i >= n4) return;
    float4 v = ((const float4*)in)[i];
    uint2 hv;
    hv.x = packpair(v.x, v.y);
    hv.y = packpair(v.z, v.w);
    ((uint2*)hi)[i] = hv;
}

__device__ __forceinline__ float blockReduceSum(float v, float* sh) {
    __syncthreads();
    int lane = threadIdx.x & 31, w = threadIdx.x >> 5;
    #pragma unroll
    for (int o = 16; o; o >>= 1) v += __shfl_xor_sync(0xffffffffu, v, o);
    if (lane == 0) sh[w] = v;
    __syncthreads();
    if (threadIdx.x == 0) {
        float s = 0.f;
        #pragma unroll
        for (int i = 0; i < 8; i++) s += sh[i];
        sh[0] = s;
    }
    __syncthreads();
    return sh[0];
}

// LayerNorm (biased variance); optionally emits split halves too
template<bool SPLIT>
__global__ __launch_bounds__(256)
void layernorm_k(const float* __restrict__ in, const float* __restrict__ g,
                 const float* __restrict__ be, float* __restrict__ out,
                 __half* __restrict__ ohi, __half* __restrict__ olo)
{
    size_t row = blockIdx.x;
    const float4* p = (const float4*)(in + row * Dm);
    int t = threadIdx.x;
    __shared__ float sh[8];

    float4 v = p[t];
    float s  = v.x + v.y + v.z + v.w;
    float sq = v.x*v.x + v.y*v.y + v.z*v.z + v.w*v.w;
    s  = blockReduceSum(s, sh);
    sq = blockReduceSum(sq, sh);
    float mean = s * (1.f / Dm);
    float var  = sq * (1.f / Dm) - mean * mean;
    float inv  = rsqrtf(var + EPSV);

    float4 gg = ((const float4*)g)[t];
    float4 bb = ((const float4*)be)[t];
    float4 o;
    o.x = gg.x * (v.x - mean) * inv + bb.x;
    o.y = gg.y * (v.y - mean) * inv + bb.y;
    o.z = gg.z * (v.z - mean) * inv + bb.z;
    o.w = gg.w * (v.w - mean) * inv + bb.w;
    ((float4*)(out + row * Dm))[t] = o;
    if (SPLIT) {
        uint2 hv, lv;
        splitpair(o.x, o.y, hv.x, lv.x);
        splitpair(o.z, o.w, hv.y, lv.y);
        ((uint2*)(ohi + row * Dm))[t] = hv;
        ((uint2*)(olo + row * Dm))[t] = lv;
    }
}

// ------------------------------- launcher ----------------------------------
static void* symaddr(const void* sym) {
    void* p = nullptr;
    cudaGetSymbolAddress(&p, sym);
    return p;
}

extern "C" void kernel_launch(void* const* d_in, const int* in_sizes, int n_in,
                              void* d_out, int out_size)
{
    const float* x    = (const float*)d_in[0];
    const int*   mask = (const int*)  d_in[1];
    const float* Wqkv = (const float*)d_in[2];
    const float* bqkv = (const float*)d_in[3];
    const float* Wo   = (const float*)d_in[4];
    const float* bo   = (const float*)d_in[5];
    const float* W1   = (const float*)d_in[6];
    const float* b1   = (const float*)d_in[7];
    const float* W2   = (const float*)d_in[8];
    const float* b2   = (const float*)d_in[9];
    const float* g1   = (const float*)d_in[10];
    const float* be1  = (const float*)d_in[11];
    const float* g2   = (const float*)d_in[12];
    const float* be2  = (const float*)d_in[13];
    float* out = (float*)d_out;

    __half* xhi = (__half*)symaddr(g_xhi);
    __half* xlo = (__half*)symaddr(g_xlo);
    __half* Wqh = (__half*)symaddr(g_Wqkvh);
    __half* Woh = (__half*)symaddr(g_Woh);
    __half* W1h = (__half*)symaddr(g_W1h);
    __half* W2h = (__half*)symaddr(g_W2h);
    __half* qh  = (__half*)symaddr(g_qh);
    __half* ql  = (__half*)symaddr(g_ql);
    __half* kh  = (__half*)symaddr(g_kh);
    __half* vth = (__half*)symaddr(g_vth);
    __half* cxh = (__half*)symaddr(g_ctxh);
    __half* cxl = (__half*)symaddr(g_ctxl);
    float*  r1  = (float*) symaddr(g_r1);
    float*  hbf = (float*) symaddr(g_h);
    __half* hhi = (__half*)symaddr(g_hh);
    __half* hlo = (__half*)symaddr(g_hl);
    __half* f1h = (__half*)symaddr(g_f1h);
    __half* f1l = (__half*)symaddr(g_f1l);
    float*  r2  = (float*) symaddr(g_r2);

    constexpr int SM128 = 3 * (2*128*80 + 128*80);     // 92160
    // flash: Q(2x18432) + K(2x18432) + V(2x17408) + mask(1024)
    constexpr int SMFA  = 2*18432 + 2*18432 + 2*17408 + 1024;  // 109568
    cudaFuncSetAttribute(mma_gemm<128,0>, cudaFuncAttributeMaxDynamicSharedMemorySize, SM128);
    cudaFuncSetAttribute(mma_gemm<128,3>, cudaFuncAttributeMaxDynamicSharedMemorySize, SM128);
    cudaFuncSetAttribute(mma_gemm<128,4>, cudaFuncAttributeMaxDynamicSharedMemorySize, SM128);
    cudaFuncSetAttribute(mma_gemm<128,5>, cudaFuncAttributeMaxDynamicSharedMemorySize, SM128);
    cudaFuncSetAttribute(flash_attn,      cudaFuncAttributeMaxDynamicSharedMemorySize, SMFA);

    // 0) split x (A operand); weights to plain fp16 (B operands)
    split_k <<<(MTOT*Dm/4 + 255)/256, 256>>>(x,    xhi, xlo, MTOT*Dm/4);
    tohalf_k<<<(3*Dm*Dm/4 + 255)/256, 256>>>(Wqkv, Wqh, 3*Dm*Dm/4);
    tohalf_k<<<(Dm*Dm/4   + 255)/256, 256>>>(Wo,   Woh, Dm*Dm/4);
    tohalf_k<<<(FFNm*Dm/4 + 255)/256, 256>>>(W1,   W1h, FFNm*Dm/4);
    tohalf_k<<<(Dm*FFNm/4 + 255)/256, 256>>>(W2,   W2h, Dm*FFNm/4);

    // 1) QKV projection -> scatter q (scaled, split) / k / v (transposed)
    mma_gemm<128,0><<<dim3(24, 32, 1), 256, SM128>>>(
        xhi, xlo, Wqh, bqkv, Dm,
        nullptr, 3*Dm, nullptr, nullptr, nullptr,
        qh, ql, kh, vth);

    // 2-4) fused flash attention -> split ctx
    flash_attn<<<dim3(8, 64), 256, SMFA>>>(
        qh, ql, kh, vth, mask, cxh, cxl);

    // 5) out proj + residual(x)
    mma_gemm<128,3><<<dim3(8, 32, 1), 256, SM128>>>(
        cxh, cxl, Woh, bo, Dm,
        x, Dm, r1, nullptr, nullptr,
        nullptr, nullptr, nullptr, nullptr);

    // 6) LN1 (+ split h)
    layernorm_k<true><<<MTOT, 256>>>(r1, g1, be1, hbf, hhi, hlo);

    // 7) FFN1 + relu -> split f1
    mma_gemm<128,4><<<dim3(32, 32, 1), 256, SM128>>>(
        hhi, hlo, W1h, b1, Dm,
        nullptr, FFNm, nullptr, f1h, f1l,
        nullptr, nullptr, nullptr, nullptr);

    // 8) FFN2 + residual(h)
    mma_gemm<128,5><<<dim3(8, 32, 1), 256, SM128>>>(
        f1h, f1l, W2h, b2, FFNm,
        hbf, Dm, r2, nullptr, nullptr,
        nullptr, nullptr, nullptr, nullptr);

    // 9) LN2 -> output
    layernorm_k<false><<<MTOT, 256>>>(r2, g2, be2, out, nullptr, nullptr);
}

// round 6
// speedup vs baseline: 5.3564x; 1.4274x over previous
#include <cuda_runtime.h>
#include <cuda_fp16.h>
#include <cstdint>

// ---------------------------------------------------------------------------
// EncoderLayer via legacy tensor cores (mma.sync m16n8k16 fp16, f32 acc).
// Round 6: pure fp16 operands everywhere (fp32 accumulate); only P in the
// flash PV product keeps a hi/lo register split. Error budget measured at
// ~2-4e-5 per rounded tensor -> expected ~1.2e-4 total (limit 1e-3).
// B=4, S=1024, D=1024, H=16, hd=64, FFN=4096.
// ---------------------------------------------------------------------------

#define Dm   1024
#define Hh   16
#define HD   64
#define FFNm 4096
#define Bb   4
#define Ss   1024
#define MTOT (Bb*Ss)
#define NEGV (-1e9f)
#define EPSV (1e-12f)

// ------------------------------ ptx helpers -------------------------------
__device__ __forceinline__ uint32_t smem_u32(const void* p) {
    uint32_t a;
    asm("{ .reg .u64 t; cvta.to.shared.u64 t, %1; cvt.u32.u64 %0, t; }"
        : "=r"(a) : "l"(p));
    return a;
}

#define CP16(dst, src) \
    asm volatile("cp.async.cg.shared.global [%0], [%1], 16;" :: "r"(dst), "l"(src))
#define CP_COMMIT() asm volatile("cp.async.commit_group;" ::: "memory")
#define CP_WAIT1()  asm volatile("cp.async.wait_group 1;" ::: "memory")

#define LDSM4(r, addr) \
    asm volatile("ldmatrix.sync.aligned.m8n8.x4.shared.b16 {%0,%1,%2,%3}, [%4];" \
        : "=r"((r)[0]), "=r"((r)[1]), "=r"((r)[2]), "=r"((r)[3]) : "r"(addr))
#define LDSM2(r, addr) \
    asm volatile("ldmatrix.sync.aligned.m8n8.x2.shared.b16 {%0,%1}, [%2];" \
        : "=r"((r)[0]), "=r"((r)[1]) : "r"(addr))

#define MMA(c, a, b) \
    asm volatile("mma.sync.aligned.m16n8k16.row.col.f32.f16.f16.f32 " \
        "{%0,%1,%2,%3},{%4,%5,%6,%7},{%8,%9},{%0,%1,%2,%3};" \
        : "+f"((c)[0]), "+f"((c)[1]), "+f"((c)[2]), "+f"((c)[3]) \
        : "r"((a)[0]), "r"((a)[1]), "r"((a)[2]), "r"((a)[3]), "r"((b)[0]), "r"((b)[1]))

// ------------------------------- scratch ----------------------------------
__device__ __half g_xh[MTOT*Dm];
__device__ __half g_Wqkvh[3*Dm*Dm];
__device__ __half g_Woh[Dm*Dm];
__device__ __half g_W1h[FFNm*Dm];
__device__ __half g_W2h[Dm*FFNm];
__device__ __half g_qh[Bb*Hh*Ss*HD];
__device__ __half g_kh[Bb*Hh*Ss*HD];
__device__ __half g_vth[Bb*Hh*Ss*HD];                       // [z][d][s]
__device__ __half g_ctxh[MTOT*Dm];
__device__ float  g_r1[MTOT*Dm];
__device__ float  g_h[MTOT*Dm];
__device__ __half g_hh[MTOT*Dm];
__device__ __half g_f1h[(size_t)MTOT*FFNm];
__device__ float  g_r2[MTOT*Dm];

// ------------------------------- pack utils -------------------------------
__device__ __forceinline__ void splitpair(float a, float b, uint32_t& h, uint32_t& l) {
    __half ha = __float2half_rn(a), hb = __float2half_rn(b);
    __half la = __float2half_rn(a - __half2float(ha));
    __half lb = __float2half_rn(b - __half2float(hb));
    h = (uint32_t)__half_as_ushort(ha) | ((uint32_t)__half_as_ushort(hb) << 16);
    l = (uint32_t)__half_as_ushort(la) | ((uint32_t)__half_as_ushort(lb) << 16);
}
__device__ __forceinline__ uint32_t packpair(float a, float b) {
    __half ha = __float2half_rn(a), hb = __float2half_rn(b);
    return (uint32_t)__half_as_ushort(ha) | ((uint32_t)__half_as_ushort(hb) << 16);
}

// ------------------------------- GEMM (HMMA) -------------------------------
// C[M,N] = A[M,K] @ B[N,K]^T; plain fp16 operands, fp32 accumulators.
// BM=128, BK=32, 256 threads = 8 warps (2 Mwarps x 4 Nwarps).
// MODE 0: qkv scatter (q scaled fp16, k fp16, v fp16 transposed)
// MODE 3/5: +bias+resid -> fp32
// MODE 4: relu+bias -> fp16
template<int BN, int MODE>
__global__ __launch_bounds__(256)
void mma_gemm(const __half* __restrict__ Ah,
              const __half* __restrict__ Bh,
              const float* __restrict__ bias, int K,
              const float* __restrict__ resid,
              int Nc, float* __restrict__ Cf,
              __half* __restrict__ Ch,
              __half* __restrict__ qh, __half* __restrict__ kh,
              __half* __restrict__ vh)
{
    constexpr int A_BYTES = 128 * 80;
    constexpr int B_BYTES = BN * 80;
    constexpr int STAGE   = A_BYTES + B_BYTES;
    constexpr int WN = BN / 4;
    constexpr int NT = WN / 8;

    const int tid = threadIdx.x;
    const int wid = tid >> 5, l = tid & 31;
    const int wm = wid >> 2, wn = wid & 3;
    const int m0 = blockIdx.y * 128;
    const int n0 = blockIdx.x * BN;

    extern __shared__ char dsm[];
    const uint32_t smem_base = smem_u32(dsm);

    uint32_t aoff[4];
    #pragma unroll
    for (int mt = 0; mt < 4; mt++)
        aoff[mt] = (uint32_t)((wm*64 + mt*16 + (l & 15)) * 80 + (l >> 4) * 16);
    uint32_t boff[NT];
    #pragma unroll
    for (int nt = 0; nt < NT; nt++)
        boff[nt] = (uint32_t)((wn*WN + nt*8 + (l & 7)) * 80 + ((l >> 3) & 1) * 16);

    float acc[4][NT][4];
    #pragma unroll
    for (int mt = 0; mt < 4; mt++)
        #pragma unroll
        for (int nt = 0; nt < NT; nt++)
            #pragma unroll
            for (int j = 0; j < 4; j++) acc[mt][nt][j] = 0.f;

    const int niter = K >> 5;

    auto load_stage = [&](int st, int k0) {
        uint32_t base = smem_base + st * STAGE;
        #pragma unroll
        for (int i = 0; i < 2; i++) {            // A: 512 chunks
            int id = tid + (i << 8);
            int r = id >> 2, c = id & 3;
            size_t g = (size_t)(m0 + r) * K + k0 + c * 8;
            CP16(base + r * 80 + c * 16, Ah + g);
        }
        #pragma unroll
        for (int i = 0; i < BN / 64; i++) {      // B: BN*4 chunks
            int id = tid + (i << 8);
            int r = id >> 2, c = id & 3;
            size_t g = (size_t)(n0 + r) * K + k0 + c * 8;
            CP16(base + A_BYTES + r * 80 + c * 16, Bh + g);
        }
    };

    load_stage(0, 0);  CP_COMMIT();
    if (niter > 1) load_stage(1, 32);
    CP_COMMIT();

    for (int it = 0; it < niter; it++) {
        CP_WAIT1();
        __syncthreads();

        int pf = it + 2;
        if (pf < niter) load_stage(pf % 3, pf << 5);
        CP_COMMIT();

        const uint32_t sAb = smem_base + (it % 3) * STAGE;
        const uint32_t sBb = sAb + A_BYTES;
        #pragma unroll
        for (int ks = 0; ks < 2; ks++) {
            uint32_t ah[4][4];
            #pragma unroll
            for (int mt = 0; mt < 4; mt++)
                LDSM4(ah[mt], sAb + aoff[mt] + ks * 32);
            #pragma unroll
            for (int nt = 0; nt < NT; nt++) {
                uint32_t bh[2];
                LDSM2(bh, sBb + boff[nt] + ks * 32);
                #pragma unroll
                for (int mt = 0; mt < 4; mt++)
                    MMA(acc[mt][nt], ah[mt], bh);
            }
        }
    }

    const int rbase = m0 + wm*64 + (l >> 2);
    const int cbase = n0 + wn*WN + 2*(l & 3);

    #pragma unroll
    for (int mt = 0; mt < 4; mt++) {
        #pragma unroll
        for (int nt = 0; nt < NT; nt++) {
            const int col = cbase + nt*8;
            #pragma unroll
            for (int half_ : {0, 1}) {
                const int row = rbase + mt*16 + half_*8;
                float v0 = acc[mt][nt][half_*2 + 0];
                float v1 = acc[mt][nt][half_*2 + 1];

                if (MODE == 0) {
                    float f0 = v0 + bias[col], f1 = v1 + bias[col + 1];
                    const int which = col >> 10;
                    const int hm = col & 1023;
                    const int hidx = hm >> 6, d = hm & 63;
                    const int b = row >> 10, s = row & 1023;
                    const int zz = (b << 4) + hidx;
                    if (which == 0) {
                        f0 *= 0.125f; f1 *= 0.125f;
                        size_t idx = ((size_t)zz * Ss + s) * 64 + d;
                        *(uint32_t*)(qh + idx) = packpair(f0, f1);
                    } else if (which == 1) {
                        size_t idx = ((size_t)zz * Ss + s) * 64 + d;
                        *(uint32_t*)(kh + idx) = packpair(f0, f1);
                    } else {
                        size_t i0 = ((size_t)zz * 64 + d) * Ss + s;
                        vh[i0]      = __float2half_rn(f0);
                        vh[i0 + Ss] = __float2half_rn(f1);
                    }
                } else if (MODE == 3 || MODE == 5) {
                    size_t idx = (size_t)row * Nc + col;
                    float2 rv = *(const float2*)(resid + idx);
                    float2 o;
                    o.x = v0 + bias[col]     + rv.x;
                    o.y = v1 + bias[col + 1] + rv.y;
                    *(float2*)(Cf + idx) = o;
                } else { // MODE 4: relu + fp16
                    size_t idx = (size_t)row * Nc + col;
                    float f0 = fmaxf(v0 + bias[col], 0.f);
                    float f1 = fmaxf(v1 + bias[col + 1], 0.f);
                    *(uint32_t*)(Ch + idx) = packpair(f0, f1);
                }
            }
        }
    }
}

// --------------------------- flash attention -------------------------------
// One CTA per (z, 128-query block). 8 warps, each owns 16 query rows.
// S = Q@K^T (fp16), key mask, online softmax,
// O += P@V^T (P split hi/lo in registers, V fp16), final 1/lsum -> fp16 ctx.
__global__ __launch_bounds__(256)
void flash_attn(const __half* __restrict__ qh_, const __half* __restrict__ kh_,
                const __half* __restrict__ vh_,
                const int* __restrict__ mask,
                __half* __restrict__ cxh)
{
    constexpr int QSTRIDE = 144;             // 64 halves + 8 pad
    constexpr int QTILE   = 128 * QSTRIDE;   // 18432 B
    constexpr int VSTRIDE = 272;             // 128 halves + 8 pad
    constexpr int VTILE   = 64 * VSTRIDE;    // 17408 B
    constexpr int NBLK    = Ss / 128;

    const int z  = blockIdx.y;               // b*16 + h
    const int q0 = blockIdx.x * 128;
    const int b  = z >> 4, h = z & 15;
    const int tid = threadIdx.x, wid = tid >> 5, l = tid & 31;

    extern __shared__ char sm[];
    const uint32_t base = smem_u32(sm);
    const uint32_t sQh = base;
    const uint32_t sKh = sQh + QTILE;        // [2 stages]
    const uint32_t sVh = sKh + 2 * QTILE;    // [2 stages]
    int* sMask = (int*)(sm + (sVh - base) + 2 * VTILE);   // [2][128]

    const __half* qhz = qh_ + (size_t)z * Ss * 64;
    const __half* khz = kh_ + (size_t)z * Ss * 64;
    const __half* vhz = vh_ + (size_t)z * 64 * Ss;
    const int*    mz  = mask + (size_t)z * Ss;

    auto load_q = [&]() {
        #pragma unroll
        for (int i = 0; i < 4; i++) {
            int id = tid + (i << 8);
            int r = id >> 3, c = id & 7;
            CP16(sQh + r * QSTRIDE + c * 16, qhz + (size_t)(q0 + r) * 64 + c * 8);
        }
    };
    auto load_kv = [&](int blk, int st) {
        int key0 = blk * 128;
        #pragma unroll
        for (int i = 0; i < 4; i++) {        // K: 128 rows x 8 chunks
            int id = tid + (i << 8);
            int r = id >> 3, c = id & 7;
            CP16(sKh + st * QTILE + r * QSTRIDE + c * 16,
                 khz + (size_t)(key0 + r) * 64 + c * 8);
        }
        #pragma unroll
        for (int i = 0; i < 4; i++) {        // V: 64 rows x 16 chunks
            int id = tid + (i << 8);
            int r = id >> 4, c = id & 15;
            CP16(sVh + st * VTILE + r * VSTRIDE + c * 16,
                 vhz + (size_t)r * Ss + key0 + c * 8);
        }
        if (tid < 128) sMask[st * 128 + tid] = mz[key0 + tid];
    };

    load_q();
    load_kv(0, 0);
    CP_COMMIT();
    load_kv(1, 1);
    CP_COMMIT();

    uint32_t qfh[4][4];
    float o[8][4];
    #pragma unroll
    for (int nt = 0; nt < 8; nt++)
        #pragma unroll
        for (int j = 0; j < 4; j++) o[nt][j] = 0.f;
    float mA = -1e30f, mB = -1e30f, lsA = 0.f, lsB = 0.f;

    const uint32_t qrow = (uint32_t)((wid*16 + (l & 15)) * QSTRIDE + (l >> 4) * 16);
    const uint32_t krow = (uint32_t)(((l & 7)) * QSTRIDE + ((l >> 3) & 1) * 16);
    const uint32_t vrow = (uint32_t)(((l & 7)) * VSTRIDE + ((l >> 3) & 1) * 16);

    for (int it = 0; it < NBLK; it++) {
        CP_WAIT1();
        __syncthreads();

        if (it == 0) {
            #pragma unroll
            for (int ks = 0; ks < 4; ks++)
                LDSM4(qfh[ks], sQh + qrow + ks * 32);
        }

        const int st = it & 1;
        const uint32_t kb = sKh + st * QTILE;

        // ---- S = Q K^T ----
        float s[16][4];
        #pragma unroll
        for (int nt = 0; nt < 16; nt++)
            #pragma unroll
            for (int j = 0; j < 4; j++) s[nt][j] = 0.f;

        #pragma unroll
        for (int ks = 0; ks < 4; ks++) {
            #pragma unroll
            for (int nt = 0; nt < 16; nt++) {
                uint32_t bh[2];
                LDSM2(bh, kb + krow + nt * 8 * QSTRIDE + ks * 32);
                MMA(s[nt], qfh[ks], bh);
            }
        }

        // ---- mask + online softmax ----
        const int* mk = sMask + st * 128;
        float mxA = -1e30f, mxB = -1e30f;
        #pragma unroll
        for (int nt = 0; nt < 16; nt++) {
            int c0 = nt*8 + (l & 3)*2;
            if (!mk[c0])     { s[nt][0] = NEGV; s[nt][2] = NEGV; }
            if (!mk[c0 + 1]) { s[nt][1] = NEGV; s[nt][3] = NEGV; }
            mxA = fmaxf(mxA, fmaxf(s[nt][0], s[nt][1]));
            mxB = fmaxf(mxB, fmaxf(s[nt][2], s[nt][3]));
        }
        mxA = fmaxf(mxA, __shfl_xor_sync(0xffffffffu, mxA, 1));
        mxA = fmaxf(mxA, __shfl_xor_sync(0xffffffffu, mxA, 2));
        mxB = fmaxf(mxB, __shfl_xor_sync(0xffffffffu, mxB, 1));
        mxB = fmaxf(mxB, __shfl_xor_sync(0xffffffffu, mxB, 2));

        float mAn = fmaxf(mA, mxA), mBn = fmaxf(mB, mxB);
        float scA = __expf(mA - mAn), scB = __expf(mB - mBn);
        mA = mAn; mB = mBn;

        float sumA = 0.f, sumB = 0.f;
        #pragma unroll
        for (int nt = 0; nt < 16; nt++) {
            s[nt][0] = __expf(s[nt][0] - mAn);
            s[nt][1] = __expf(s[nt][1] - mAn);
            s[nt][2] = __expf(s[nt][2] - mBn);
            s[nt][3] = __expf(s[nt][3] - mBn);
            sumA += s[nt][0] + s[nt][1];
            sumB += s[nt][2] + s[nt][3];
        }
        sumA += __shfl_xor_sync(0xffffffffu, sumA, 1);
        sumA += __shfl_xor_sync(0xffffffffu, sumA, 2);
        sumB += __shfl_xor_sync(0xffffffffu, sumB, 1);
        sumB += __shfl_xor_sync(0xffffffffu, sumB, 2);
        lsA = lsA * scA + sumA;
        lsB = lsB * scB + sumB;

        #pragma unroll
        for (int nt = 0; nt < 8; nt++) {
            o[nt][0] *= scA; o[nt][1] *= scA;
            o[nt][2] *= scB; o[nt][3] *= scB;
        }

        // ---- O += P V^T (P split hi/lo in registers, V fp16) ----
        const uint32_t vb = sVh + st * VTILE;
        #pragma unroll
        for (int ks = 0; ks < 8; ks++) {
            uint32_t ah[4], al[4];
            splitpair(s[2*ks][0],   s[2*ks][1],   ah[0], al[0]);
            splitpair(s[2*ks][2],   s[2*ks][3],   ah[1], al[1]);
            splitpair(s[2*ks+1][0], s[2*ks+1][1], ah[2], al[2]);
            splitpair(s[2*ks+1][2], s[2*ks+1][3], ah[3], al[3]);
            #pragma unroll
            for (int nt = 0; nt < 8; nt++) {
                uint32_t vh2[2];
                LDSM2(vh2, vb + vrow + nt * 8 * VSTRIDE + ks * 32);
                MMA(o[nt], ah, vh2);
                MMA(o[nt], al, vh2);
            }
        }

        __syncthreads();
        if (it + 2 < NBLK) load_kv(it + 2, st);
        CP_COMMIT();
    }

    // ---- epilogue: scale by 1/lsum, fp16 ctx[b, s, h*64+d] ----
    const float invA = 1.f / lsA, invB = 1.f / lsB;
    const int rowA = (b << 10) + q0 + wid*16 + (l >> 2);
    const int rowB = rowA + 8;
    #pragma unroll
    for (int nt = 0; nt < 8; nt++) {
        const int col = (h << 6) + nt*8 + (l & 3)*2;
        *(uint32_t*)(cxh + (size_t)rowA * Dm + col) =
            packpair(o[nt][0] * invA, o[nt][1] * invA);
        *(uint32_t*)(cxh + (size_t)rowB * Dm + col) =
            packpair(o[nt][2] * invB, o[nt][3] * invB);
    }
}

// ------------------------------- aux kernels -------------------------------
__global__ __launch_bounds__(256)
void tohalf_k(const float* __restrict__ in, __half* __restrict__ hi, int n4)
{
    int i = blockIdx.x * 256 + threadIdx.x;
    if (i >= n4) return;
    float4 v = ((const float4*)in)[i];
    uint2 hv;
    hv.x = packpair(v.x, v.y);
    hv.y = packpair(v.z, v.w);
    ((uint2*)hi)[i] = hv;
}

__device__ __forceinline__ float blockReduceSum(float v, float* sh) {
    __syncthreads();
    int lane = threadIdx.x & 31, w = threadIdx.x >> 5;
    #pragma unroll
    for (int o = 16; o; o >>= 1) v += __shfl_xor_sync(0xffffffffu, v, o);
    if (lane == 0) sh[w] = v;
    __syncthreads();
    if (threadIdx.x == 0) {
        float s = 0.f;
        #pragma unroll
        for (int i = 0; i < 8; i++) s += sh[i];
        sh[0] = s;
    }
    __syncthreads();
    return sh[0];
}

// LayerNorm (biased variance); optionally emits fp16 copy too
template<bool EMIT16>
__global__ __launch_bounds__(256)
void layernorm_k(const float* __restrict__ in, const float* __restrict__ g,
                 const float* __restrict__ be, float* __restrict__ out,
                 __half* __restrict__ o16)
{
    size_t row = blockIdx.x;
    const float4* p = (const float4*)(in + row * Dm);
    int t = threadIdx.x;
    __shared__ float sh[8];

    float4 v = p[t];
    float s  = v.x + v.y + v.z + v.w;
    float sq = v.x*v.x + v.y*v.y + v.z*v.z + v.w*v.w;
    s  = blockReduceSum(s, sh);
    sq = blockReduceSum(sq, sh);
    float mean = s * (1.f / Dm);
    float var  = sq * (1.f / Dm) - mean * mean;
    float inv  = rsqrtf(var + EPSV);

    float4 gg = ((const float4*)g)[t];
    float4 bb = ((const float4*)be)[t];
    float4 o;
    o.x = gg.x * (v.x - mean) * inv + bb.x;
    o.y = gg.y * (v.y - mean) * inv + bb.y;
    o.z = gg.z * (v.z - mean) * inv + bb.z;
    o.w = gg.w * (v.w - mean) * inv + bb.w;
    ((float4*)(out + row * Dm))[t] = o;
    if (EMIT16) {
        uint2 hv;
        hv.x = packpair(o.x, o.y);
        hv.y = packpair(o.z, o.w);
        ((uint2*)(o16 + row * Dm))[t] = hv;
    }
}

// ------------------------------- launcher ----------------------------------
static void* symaddr(const void* sym) {
    void* p = nullptr;
    cudaGetSymbolAddress(&p, sym);
    return p;
}

extern "C" void kernel_launch(void* const* d_in, const int* in_sizes, int n_in,
                              void* d_out, int out_size)
{
    const float* x    = (const float*)d_in[0];
    const int*   mask = (const int*)  d_in[1];
    const float* Wqkv = (const float*)d_in[2];
    const float* bqkv = (const float*)d_in[3];
    const float* Wo   = (const float*)d_in[4];
    const float* bo   = (const float*)d_in[5];
    const float* W1   = (const float*)d_in[6];
    const float* b1   = (const float*)d_in[7];
    const float* W2   = (const float*)d_in[8];
    const float* b2   = (const float*)d_in[9];
    const float* g1   = (const float*)d_in[10];
    const float* be1  = (const float*)d_in[11];
    const float* g2   = (const float*)d_in[12];
    const float* be2  = (const float*)d_in[13];
    float* out = (float*)d_out;

    __half* xh  = (__half*)symaddr(g_xh);
    __half* Wqh = (__half*)symaddr(g_Wqkvh);
    __half* Woh = (__half*)symaddr(g_Woh);
    __half* W1h = (__half*)symaddr(g_W1h);
    __half* W2h = (__half*)symaddr(g_W2h);
    __half* qh  = (__half*)symaddr(g_qh);
    __half* kh  = (__half*)symaddr(g_kh);
    __half* vth = (__half*)symaddr(g_vth);
    __half* cxh = (__half*)symaddr(g_ctxh);
    float*  r1  = (float*) symaddr(g_r1);
    float*  hbf = (float*) symaddr(g_h);
    __half* hhi = (__half*)symaddr(g_hh);
    __half* f1h = (__half*)symaddr(g_f1h);
    float*  r2  = (float*) symaddr(g_r2);

    constexpr int SM128 = 3 * (128*80 + 128*80);       // 61440
    // flash: Q(18432) + K(2x18432) + V(2x17408) + mask(1024)
    constexpr int SMFA  = 18432 + 2*18432 + 2*17408 + 1024;  // 91136
    cudaFuncSetAttribute(mma_gemm<128,0>, cudaFuncAttributeMaxDynamicSharedMemorySize, SM128);
    cudaFuncSetAttribute(mma_gemm<128,3>, cudaFuncAttributeMaxDynamicSharedMemorySize, SM128);
    cudaFuncSetAttribute(mma_gemm<128,4>, cudaFuncAttributeMaxDynamicSharedMemorySize, SM128);
    cudaFuncSetAttribute(mma_gemm<128,5>, cudaFuncAttributeMaxDynamicSharedMemorySize, SM128);
    cudaFuncSetAttribute(flash_attn,      cudaFuncAttributeMaxDynamicSharedMemorySize, SMFA);

    // 0) convert x + weights to fp16
    tohalf_k<<<(MTOT*Dm/4 + 255)/256, 256>>>(x,    xh,  MTOT*Dm/4);
    tohalf_k<<<(3*Dm*Dm/4 + 255)/256, 256>>>(Wqkv, Wqh, 3*Dm*Dm/4);
    tohalf_k<<<(Dm*Dm/4   + 255)/256, 256>>>(Wo,   Woh, Dm*Dm/4);
    tohalf_k<<<(FFNm*Dm/4 + 255)/256, 256>>>(W1,   W1h, FFNm*Dm/4);
    tohalf_k<<<(Dm*FFNm/4 + 255)/256, 256>>>(W2,   W2h, Dm*FFNm/4);

    // 1) QKV projection -> scatter q (scaled) / k / v (transposed)
    mma_gemm<128,0><<<dim3(24, 32, 1), 256, SM128>>>(
        xh, Wqh, bqkv, Dm,
        nullptr, 3*Dm, nullptr, nullptr,
        qh, kh, vth);

    // 2-4) fused flash attention -> fp16 ctx
    flash_attn<<<dim3(8, 64), 256, SMFA>>>(
        qh, kh, vth, mask, cxh);

    // 5) out proj + residual(x)
    mma_gemm<128,3><<<dim3(8, 32, 1), 256, SM128>>>(
        cxh, Woh, bo, Dm,
        x, Dm, r1, nullptr,
        nullptr, nullptr, nullptr);

    // 6) LN1 (+ fp16 h)
    layernorm_k<true><<<MTOT, 256>>>(r1, g1, be1, hbf, hhi);

    // 7) FFN1 + relu -> fp16 f1
    mma_gemm<128,4><<<dim3(32, 32, 1), 256, SM128>>>(
        hhi, W1h, b1, Dm,
        nullptr, FFNm, nullptr, f1h,
        nullptr, nullptr, nullptr);

    // 8) FFN2 + residual(h)
    mma_gemm<128,5><<<dim3(8, 32, 1), 256, SM128>>>(
        f1h, W2h, b2, FFNm,
        hbf, Dm, r2, nullptr,
        nullptr, nullptr, nullptr);

    // 9) LN2 -> output
    layernorm_k<false><<<MTOT, 256>>>(r2, g2, be2, out, nullptr);
}

// round 7
// speedup vs baseline: 6.1032x; 1.1394x over previous
#include <cuda_runtime.h>
#include <cuda_fp16.h>
#include <cstdint>

// ---------------------------------------------------------------------------
// EncoderLayer via legacy tensor cores (mma.sync m16n8k16 fp16, f32 acc).
// Round 7: pure fp16 operands everywhere (incl. P in flash), LDSM4-paired
// B-fragment loads, merged weight conversion.
// B=4, S=1024, D=1024, H=16, hd=64, FFN=4096.
// ---------------------------------------------------------------------------

#define Dm   1024
#define Hh   16
#define HD   64
#define FFNm 4096
#define Bb   4
#define Ss   1024
#define MTOT (Bb*Ss)
#define NEGV (-1e9f)
#define EPSV (1e-12f)

// ------------------------------ ptx helpers -------------------------------
__device__ __forceinline__ uint32_t smem_u32(const void* p) {
    uint32_t a;
    asm("{ .reg .u64 t; cvta.to.shared.u64 t, %1; cvt.u32.u64 %0, t; }"
        : "=r"(a) : "l"(p));
    return a;
}

#define CP16(dst, src) \
    asm volatile("cp.async.cg.shared.global [%0], [%1], 16;" :: "r"(dst), "l"(src))
#define CP_COMMIT() asm volatile("cp.async.commit_group;" ::: "memory")
#define CP_WAIT1()  asm volatile("cp.async.wait_group 1;" ::: "memory")

#define LDSM4(r, addr) \
    asm volatile("ldmatrix.sync.aligned.m8n8.x4.shared.b16 {%0,%1,%2,%3}, [%4];" \
        : "=r"((r)[0]), "=r"((r)[1]), "=r"((r)[2]), "=r"((r)[3]) : "r"(addr))

#define MMA(c, a, b) \
    asm volatile("mma.sync.aligned.m16n8k16.row.col.f32.f16.f16.f32 " \
        "{%0,%1,%2,%3},{%4,%5,%6,%7},{%8,%9},{%0,%1,%2,%3};" \
        : "+f"((c)[0]), "+f"((c)[1]), "+f"((c)[2]), "+f"((c)[3]) \
        : "r"((a)[0]), "r"((a)[1]), "r"((a)[2]), "r"((a)[3]), "r"((b)[0]), "r"((b)[1]))

// ------------------------------- scratch ----------------------------------
__device__ __half g_xh[MTOT*Dm];
__device__ __half g_Wqkvh[3*Dm*Dm];
__device__ __half g_Woh[Dm*Dm];
__device__ __half g_W1h[FFNm*Dm];
__device__ __half g_W2h[Dm*FFNm];
__device__ __half g_qh[Bb*Hh*Ss*HD];
__device__ __half g_kh[Bb*Hh*Ss*HD];
__device__ __half g_vth[Bb*Hh*Ss*HD];                       // [z][d][s]
__device__ __half g_ctxh[MTOT*Dm];
__device__ float  g_r1[MTOT*Dm];
__device__ float  g_h[MTOT*Dm];
__device__ __half g_hh[MTOT*Dm];
__device__ __half g_f1h[(size_t)MTOT*FFNm];
__device__ float  g_r2[MTOT*Dm];

// ------------------------------- pack utils -------------------------------
__device__ __forceinline__ uint32_t packpair(float a, float b) {
    __half ha = __float2half_rn(a), hb = __float2half_rn(b);
    return (uint32_t)__half_as_ushort(ha) | ((uint32_t)__half_as_ushort(hb) << 16);
}

// ------------------------------- GEMM (HMMA) -------------------------------
// C[M,N] = A[M,K] @ B[N,K]^T; plain fp16 operands, fp32 accumulators.
// BM=128, BK=32, 256 threads = 8 warps (2 Mwarps x 4 Nwarps).
// B fragments loaded pairwise via ldmatrix.x4 (two n8 tiles per op).
// MODE 0: qkv scatter; MODE 3/5: +bias+resid -> fp32; MODE 4: relu -> fp16.
template<int BN, int MODE>
__global__ __launch_bounds__(256)
void mma_gemm(const __half* __restrict__ Ah,
              const __half* __restrict__ Bh,
              const float* __restrict__ bias, int K,
              const float* __restrict__ resid,
              int Nc, float* __restrict__ Cf,
              __half* __restrict__ Ch,
              __half* __restrict__ qh, __half* __restrict__ kh,
              __half* __restrict__ vh)
{
    constexpr int A_BYTES = 128 * 80;
    constexpr int B_BYTES = BN * 80;
    constexpr int STAGE   = A_BYTES + B_BYTES;
    constexpr int WN = BN / 4;
    constexpr int NT = WN / 8;          // 4
    constexpr int NP = NT / 2;          // paired ldsm4 count

    const int tid = threadIdx.x;
    const int wid = tid >> 5, l = tid & 31;
    const int wm = wid >> 2, wn = wid & 3;
    const int m0 = blockIdx.y * 128;
    const int n0 = blockIdx.x * BN;

    extern __shared__ char dsm[];
    const uint32_t smem_base = smem_u32(dsm);

    uint32_t aoff[4];
    #pragma unroll
    for (int mt = 0; mt < 4; mt++)
        aoff[mt] = (uint32_t)((wm*64 + mt*16 + (l & 15)) * 80 + (l >> 4) * 16);
    // paired B: lanes 0-7 rows+0 chunk0, 8-15 rows+0 chunk1,
    //           16-23 rows+8 chunk0, 24-31 rows+8 chunk1
    uint32_t boff[NP];
    #pragma unroll
    for (int np = 0; np < NP; np++)
        boff[np] = (uint32_t)((wn*WN + np*16 + (l & 7) + ((l >> 4) & 1) * 8) * 80
                              + ((l >> 3) & 1) * 16);

    float acc[4][NT][4];
    #pragma unroll
    for (int mt = 0; mt < 4; mt++)
        #pragma unroll
        for (int nt = 0; nt < NT; nt++)
            #pragma unroll
            for (int j = 0; j < 4; j++) acc[mt][nt][j] = 0.f;

    const int niter = K >> 5;

    auto load_stage = [&](int st, int k0) {
        uint32_t base = smem_base + st * STAGE;
        #pragma unroll
        for (int i = 0; i < 2; i++) {
            int id = tid + (i << 8);
            int r = id >> 2, c = id & 3;
            CP16(base + r * 80 + c * 16, Ah + (size_t)(m0 + r) * K + k0 + c * 8);
        }
        #pragma unroll
        for (int i = 0; i < BN / 64; i++) {
            int id = tid + (i << 8);
            int r = id >> 2, c = id & 3;
            CP16(base + A_BYTES + r * 80 + c * 16, Bh + (size_t)(n0 + r) * K + k0 + c * 8);
        }
    };

    load_stage(0, 0);  CP_COMMIT();
    if (niter > 1) load_stage(1, 32);
    CP_COMMIT();

    for (int it = 0; it < niter; it++) {
        CP_WAIT1();
        __syncthreads();

        int pf = it + 2;
        if (pf < niter) load_stage(pf % 3, pf << 5);
        CP_COMMIT();

        const uint32_t sAb = smem_base + (it % 3) * STAGE;
        const uint32_t sBb = sAb + A_BYTES;
        #pragma unroll
        for (int ks = 0; ks < 2; ks++) {
            uint32_t ah[4][4];
            #pragma unroll
            for (int mt = 0; mt < 4; mt++)
                LDSM4(ah[mt], sAb + aoff[mt] + ks * 32);
            #pragma unroll
            for (int np = 0; np < NP; np++) {
                uint32_t bq[4];
                LDSM4(bq, sBb + boff[np] + ks * 32);
                #pragma unroll
                for (int mt = 0; mt < 4; mt++) {
                    MMA(acc[mt][2*np],   ah[mt], (bq + 0));
                    MMA(acc[mt][2*np+1], ah[mt], (bq + 2));
                }
            }
        }
    }

    const int rbase = m0 + wm*64 + (l >> 2);
    const int cbase = n0 + wn*WN + 2*(l & 3);

    #pragma unroll
    for (int mt = 0; mt < 4; mt++) {
        #pragma unroll
        for (int nt = 0; nt < NT; nt++) {
            const int col = cbase + nt*8;
            #pragma unroll
            for (int half_ : {0, 1}) {
                const int row = rbase + mt*16 + half_*8;
                float v0 = acc[mt][nt][half_*2 + 0];
                float v1 = acc[mt][nt][half_*2 + 1];

                if (MODE == 0) {
                    float f0 = v0 + bias[col], f1 = v1 + bias[col + 1];
                    const int which = col >> 10;
                    const int hm = col & 1023;
                    const int hidx = hm >> 6, d = hm & 63;
                    const int b = row >> 10, s = row & 1023;
                    const int zz = (b << 4) + hidx;
                    if (which == 0) {
                        f0 *= 0.125f; f1 *= 0.125f;
                        size_t idx = ((size_t)zz * Ss + s) * 64 + d;
                        *(uint32_t*)(qh + idx) = packpair(f0, f1);
                    } else if (which == 1) {
                        size_t idx = ((size_t)zz * Ss + s) * 64 + d;
                        *(uint32_t*)(kh + idx) = packpair(f0, f1);
                    } else {
                        size_t i0 = ((size_t)zz * 64 + d) * Ss + s;
                        vh[i0]      = __float2half_rn(f0);
                        vh[i0 + Ss] = __float2half_rn(f1);
                    }
                } else if (MODE == 3 || MODE == 5) {
                    size_t idx = (size_t)row * Nc + col;
                    float2 rv = *(const float2*)(resid + idx);
                    float2 o;
                    o.x = v0 + bias[col]     + rv.x;
                    o.y = v1 + bias[col + 1] + rv.y;
                    *(float2*)(Cf + idx) = o;
                } else { // MODE 4: relu + fp16
                    size_t idx = (size_t)row * Nc + col;
                    float f0 = fmaxf(v0 + bias[col], 0.f);
                    float f1 = fmaxf(v1 + bias[col + 1], 0.f);
                    *(uint32_t*)(Ch + idx) = packpair(f0, f1);
                }
            }
        }
    }
}

// --------------------------- flash attention -------------------------------
// One CTA per (z, 128-query block). 8 warps, each owns 16 query rows.
// S = Q@K^T (fp16), key mask, online softmax, O += P@V^T (P fp16),
// final 1/lsum -> fp16 ctx. K/V fragments via paired ldmatrix.x4.
__global__ __launch_bounds__(256)
void flash_attn(const __half* __restrict__ qh_, const __half* __restrict__ kh_,
                const __half* __restrict__ vh_,
                const int* __restrict__ mask,
                __half* __restrict__ cxh)
{
    constexpr int QSTRIDE = 144;             // 64 halves + 8 pad
    constexpr int QTILE   = 128 * QSTRIDE;   // 18432 B
    constexpr int VSTRIDE = 272;             // 128 halves + 8 pad
    constexpr int VTILE   = 64 * VSTRIDE;    // 17408 B
    constexpr int NBLK    = Ss / 128;

    const int z  = blockIdx.y;               // b*16 + h
    const int q0 = blockIdx.x * 128;
    const int b  = z >> 4, h = z & 15;
    const int tid = threadIdx.x, wid = tid >> 5, l = tid & 31;

    extern __shared__ char sm[];
    const uint32_t base = smem_u32(sm);
    const uint32_t sQh = base;
    const uint32_t sKh = sQh + QTILE;        // [2 stages]
    const uint32_t sVh = sKh + 2 * QTILE;    // [2 stages]
    int* sMask = (int*)(sm + (sVh - base) + 2 * VTILE);   // [2][128]

    const __half* qhz = qh_ + (size_t)z * Ss * 64;
    const __half* khz = kh_ + (size_t)z * Ss * 64;
    const __half* vhz = vh_ + (size_t)z * 64 * Ss;
    const int*    mz  = mask + (size_t)z * Ss;

    auto load_q = [&]() {
        #pragma unroll
        for (int i = 0; i < 4; i++) {
            int id = tid + (i << 8);
            int r = id >> 3, c = id & 7;
            CP16(sQh + r * QSTRIDE + c * 16, qhz + (size_t)(q0 + r) * 64 + c * 8);
        }
    };
    auto load_kv = [&](int blk, int st) {
        int key0 = blk * 128;
        #pragma unroll
        for (int i = 0; i < 4; i++) {        // K: 128 rows x 8 chunks
            int id = tid + (i << 8);
            int r = id >> 3, c = id & 7;
            CP16(sKh + st * QTILE + r * QSTRIDE + c * 16,
                 khz + (size_t)(key0 + r) * 64 + c * 8);
        }
        #pragma unroll
        for (int i = 0; i < 4; i++) {        // V: 64 rows x 16 chunks
            int id = tid + (i << 8);
            int r = id >> 4, c = id & 15;
            CP16(sVh + st * VTILE + r * VSTRIDE + c * 16,
                 vhz + (size_t)r * Ss + key0 + c * 8);
        }
        if (tid < 128) sMask[st * 128 + tid] = mz[key0 + tid];
    };

    load_q();
    load_kv(0, 0);
    CP_COMMIT();
    load_kv(1, 1);
    CP_COMMIT();

    uint32_t qfh[4][4];
    float o[8][4];
    #pragma unroll
    for (int nt = 0; nt < 8; nt++)
        #pragma unroll
        for (int j = 0; j < 4; j++) o[nt][j] = 0.f;
    float mA = -1e30f, mB = -1e30f, lsA = 0.f, lsB = 0.f;

    const uint32_t qrow  = (uint32_t)((wid*16 + (l & 15)) * QSTRIDE + (l >> 4) * 16);
    // paired fragment addressing (two n8 tiles per ldmatrix.x4)
    const uint32_t krow4 = (uint32_t)(((l & 7) + ((l >> 4) & 1) * 8) * QSTRIDE
                                      + ((l >> 3) & 1) * 16);
    const uint32_t vrow4 = (uint32_t)(((l & 7) + ((l >> 4) & 1) * 8) * VSTRIDE
                                      + ((l >> 3) & 1) * 16);

    for (int it = 0; it < NBLK; it++) {
        CP_WAIT1();
        __syncthreads();

        if (it == 0) {
            #pragma unroll
            for (int ks = 0; ks < 4; ks++)
                LDSM4(qfh[ks], sQh + qrow + ks * 32);
        }

        const int st = it & 1;
        const uint32_t kb = sKh + st * QTILE;

        // ---- S = Q K^T ----
        float s[16][4];
        #pragma unroll
        for (int nt = 0; nt < 16; nt++)
            #pragma unroll
            for (int j = 0; j < 4; j++) s[nt][j] = 0.f;

        #pragma unroll
        for (int ks = 0; ks < 4; ks++) {
            #pragma unroll
            for (int np = 0; np < 8; np++) {
                uint32_t bq[4];
                LDSM4(bq, kb + krow4 + np * 16 * QSTRIDE + ks * 32);
                MMA(s[2*np],   qfh[ks], (bq + 0));
                MMA(s[2*np+1], qfh[ks], (bq + 2));
            }
        }

        // ---- mask + online softmax ----
        const int* mk = sMask + st * 128;
        float mxA = -1e30f, mxB = -1e30f;
        #pragma unroll
        for (int nt = 0; nt < 16; nt++) {
            int c0 = nt*8 + (l & 3)*2;
            if (!mk[c0])     { s[nt][0] = NEGV; s[nt][2] = NEGV; }
            if (!mk[c0 + 1]) { s[nt][1] = NEGV; s[nt][3] = NEGV; }
            mxA = fmaxf(mxA, fmaxf(s[nt][0], s[nt][1]));
            mxB = fmaxf(mxB, fmaxf(s[nt][2], s[nt][3]));
        }
        mxA = fmaxf(mxA, __shfl_xor_sync(0xffffffffu, mxA, 1));
        mxA = fmaxf(mxA, __shfl_xor_sync(0xffffffffu, mxA, 2));
        mxB = fmaxf(mxB, __shfl_xor_sync(0xffffffffu, mxB, 1));
        mxB = fmaxf(mxB, __shfl_xor_sync(0xffffffffu, mxB, 2));

        float mAn = fmaxf(mA, mxA), mBn = fmaxf(mB, mxB);
        float scA = __expf(mA - mAn), scB = __expf(mB - mBn);
        mA = mAn; mB = mBn;

        float sumA = 0.f, sumB = 0.f;
        #pragma unroll
        for (int nt = 0; nt < 16; nt++) {
            s[nt][0] = __expf(s[nt][0] - mAn);
            s[nt][1] = __expf(s[nt][1] - mAn);
            s[nt][2] = __expf(s[nt][2] - mBn);
            s[nt][3] = __expf(s[nt][3] - mBn);
            sumA += s[nt][0] + s[nt][1];
            sumB += s[nt][2] + s[nt][3];
        }
        sumA += __shfl_xor_sync(0xffffffffu, sumA, 1);
        sumA += __shfl_xor_sync(0xffffffffu, sumA, 2);
        sumB += __shfl_xor_sync(0xffffffffu, sumB, 1);
        sumB += __shfl_xor_sync(0xffffffffu, sumB, 2);
        lsA = lsA * scA + sumA;
        lsB = lsB * scB + sumB;

        #pragma unroll
        for (int nt = 0; nt < 8; nt++) {
            o[nt][0] *= scA; o[nt][1] *= scA;
            o[nt][2] *= scB; o[nt][3] *= scB;
        }

        // ---- O += P V^T (P packed fp16 in registers, V fp16) ----
        const uint32_t vb = sVh + st * VTILE;
        #pragma unroll
        for (int ks = 0; ks < 8; ks++) {
            uint32_t ah[4];
            ah[0] = packpair(s[2*ks][0],   s[2*ks][1]);
            ah[1] = packpair(s[2*ks][2],   s[2*ks][3]);
            ah[2] = packpair(s[2*ks+1][0], s[2*ks+1][1]);
            ah[3] = packpair(s[2*ks+1][2], s[2*ks+1][3]);
            #pragma unroll
            for (int np = 0; np < 4; np++) {
                uint32_t vq[4];
                LDSM4(vq, vb + vrow4 + np * 16 * VSTRIDE + ks * 32);
                MMA(o[2*np],   ah, (vq + 0));
                MMA(o[2*np+1], ah, (vq + 2));
            }
        }

        __syncthreads();
        if (it + 2 < NBLK) load_kv(it + 2, st);
        CP_COMMIT();
    }

    // ---- epilogue: scale by 1/lsum, fp16 ctx[b, s, h*64+d] ----
    const float invA = 1.f / lsA, invB = 1.f / lsB;
    const int rowA = (b << 10) + q0 + wid*16 + (l >> 2);
    const int rowB = rowA + 8;
    #pragma unroll
    for (int nt = 0; nt < 8; nt++) {
        const int col = (h << 6) + nt*8 + (l & 3)*2;
        *(uint32_t*)(cxh + (size_t)rowA * Dm + col) =
            packpair(o[nt][0] * invA, o[nt][1] * invA);
        *(uint32_t*)(cxh + (size_t)rowB * Dm + col) =
            packpair(o[nt][2] * invB, o[nt][3] * invB);
    }
}

// ------------------------------- aux kernels -------------------------------
__global__ __launch_bounds__(256)
void tohalf_k(const float* __restrict__ in, __half* __restrict__ hi, int n4)
{
    int i = blockIdx.x * 256 + threadIdx.x;
    if (i >= n4) return;
    float4 v = ((const float4*)in)[i];
    uint2 hv;
    hv.x = packpair(v.x, v.y);
    hv.y = packpair(v.z, v.w);
    ((uint2*)hi)[i] = hv;
}

// all four weight tensors in one launch (segments in float4 units)
__global__ __launch_bounds__(256)
void tohalf_weights(const float* __restrict__ w0, __half* __restrict__ d0,
                    const float* __restrict__ w1, __half* __restrict__ d1,
                    const float* __restrict__ w2, __half* __restrict__ d2,
                    const float* __restrict__ w3, __half* __restrict__ d3)
{
    constexpr int N0 = 3*Dm*Dm/4, N1 = Dm*Dm/4, N2 = FFNm*Dm/4, N3 = Dm*FFNm/4;
    int i = blockIdx.x * 256 + threadIdx.x;
    const float* src; __half* dst; int off;
    if (i < N0)                { src = w0; dst = d0; off = i; }
    else if (i < N0+N1)        { src = w1; dst = d1; off = i - N0; }
    else if (i < N0+N1+N2)     { src = w2; dst = d2; off = i - N0 - N1; }
    else if (i < N0+N1+N2+N3)  { src = w3; dst = d3; off = i - N0 - N1 - N2; }
    else return;
    float4 v = ((const float4*)src)[off];
    uint2 hv;
    hv.x = packpair(v.x, v.y);
    hv.y = packpair(v.z, v.w);
    ((uint2*)dst)[off] = hv;
}

__device__ __forceinline__ float blockReduceSum(float v, float* sh) {
    __syncthreads();
    int lane = threadIdx.x & 31, w = threadIdx.x >> 5;
    #pragma unroll
    for (int o = 16; o; o >>= 1) v += __shfl_xor_sync(0xffffffffu, v, o);
    if (lane == 0) sh[w] = v;
    __syncthreads();
    if (threadIdx.x == 0) {
        float s = 0.f;
        #pragma unroll
        for (int i = 0; i < 8; i++) s += sh[i];
        sh[0] = s;
    }
    __syncthreads();
    return sh[0];
}

// LayerNorm (biased variance); optionally emits fp16 copy too
template<bool EMIT16>
__global__ __launch_bounds__(256)
void layernorm_k(const float* __restrict__ in, const float* __restrict__ g,
                 const float* __restrict__ be, float* __restrict__ out,
                 __half* __restrict__ o16)
{
    size_t row = blockIdx.x;
    const float4* p = (const float4*)(in + row * Dm);
    int t = threadIdx.x;
    __shared__ float sh[8];

    float4 v = p[t];
    float s  = v.x + v.y + v.z + v.w;
    float sq = v.x*v.x + v.y*v.y + v.z*v.z + v.w*v.w;
    s  = blockReduceSum(s, sh);
    sq = blockReduceSum(sq, sh);
    float mean = s * (1.f / Dm);
    float var  = sq * (1.f / Dm) - mean * mean;
    float inv  = rsqrtf(var + EPSV);

    float4 gg = ((const float4*)g)[t];
    float4 bb = ((const float4*)be)[t];
    float4 o;
    o.x = gg.x * (v.x - mean) * inv + bb.x;
    o.y = gg.y * (v.y - mean) * inv + bb.y;
    o.z = gg.z * (v.z - mean) * inv + bb.z;
    o.w = gg.w * (v.w - mean) * inv + bb.w;
    ((float4*)(out + row * Dm))[t] = o;
    if (EMIT16) {
        uint2 hv;
        hv.x = packpair(o.x, o.y);
        hv.y = packpair(o.z, o.w);
        ((uint2*)(o16 + row * Dm))[t] = hv;
    }
}

// ------------------------------- launcher ----------------------------------
static void* symaddr(const void* sym) {
    void* p = nullptr;
    cudaGetSymbolAddress(&p, sym);
    return p;
}

extern "C" void kernel_launch(void* const* d_in, const int* in_sizes, int n_in,
                              void* d_out, int out_size)
{
    const float* x    = (const float*)d_in[0];
    const int*   mask = (const int*)  d_in[1];
    const float* Wqkv = (const float*)d_in[2];
    const float* bqkv = (const float*)d_in[3];
    const float* Wo   = (const float*)d_in[4];
    const float* bo   = (const float*)d_in[5];
    const float* W1   = (const float*)d_in[6];
    const float* b1   = (const float*)d_in[7];
    const float* W2   = (const float*)d_in[8];
    const float* b2   = (const float*)d_in[9];
    const float* g1   = (const float*)d_in[10];
    const float* be1  = (const float*)d_in[11];
    const float* g2   = (const float*)d_in[12];
    const float* be2  = (const float*)d_in[13];
    float* out = (float*)d_out;

    __half* xh  = (__half*)symaddr(g_xh);
    __half* Wqh = (__half*)symaddr(g_Wqkvh);
    __half* Woh = (__half*)symaddr(g_Woh);
    __half* W1h = (__half*)symaddr(g_W1h);
    __half* W2h = (__half*)symaddr(g_W2h);
    __half* qh  = (__half*)symaddr(g_qh);
    __half* kh  = (__half*)symaddr(g_kh);
    __half* vth = (__half*)symaddr(g_vth);
    __half* cxh = (__half*)symaddr(g_ctxh);
    float*  r1  = (float*) symaddr(g_r1);
    float*  hbf = (float*) symaddr(g_h);
    __half* hhi = (__half*)symaddr(g_hh);
    __half* f1h = (__half*)symaddr(g_f1h);
    float*  r2  = (float*) symaddr(g_r2);

    constexpr int SM128 = 3 * (128*80 + 128*80);       // 61440
    constexpr int SMFA  = 18432 + 2*18432 + 2*17408 + 1024;  // 91136
    cudaFuncSetAttribute(mma_gemm<128,0>, cudaFuncAttributeMaxDynamicSharedMemorySize, SM128);
    cudaFuncSetAttribute(mma_gemm<128,3>, cudaFuncAttributeMaxDynamicSharedMemorySize, SM128);
    cudaFuncSetAttribute(mma_gemm<128,4>, cudaFuncAttributeMaxDynamicSharedMemorySize, SM128);
    cudaFuncSetAttribute(mma_gemm<128,5>, cudaFuncAttributeMaxDynamicSharedMemorySize, SM128);
    cudaFuncSetAttribute(flash_attn,      cudaFuncAttributeMaxDynamicSharedMemorySize, SMFA);

    // 0) convert x + all weights to fp16 (weights merged into one launch)
    tohalf_k<<<(MTOT*Dm/4 + 255)/256, 256>>>(x, xh, MTOT*Dm/4);
    {
        constexpr int NW4 = (3*Dm*Dm + Dm*Dm + FFNm*Dm + Dm*FFNm) / 4;
        tohalf_weights<<<(NW4 + 255)/256, 256>>>(Wqkv, Wqh, Wo, Woh, W1, W1h, W2, W2h);
    }

    // 1) QKV projection -> scatter q (scaled) / k / v (transposed)
    mma_gemm<128,0><<<dim3(24, 32, 1), 256, SM128>>>(
        xh, Wqh, bqkv, Dm,
        nullptr, 3*Dm, nullptr, nullptr,
        qh, kh, vth);

    // 2-4) fused flash attention -> fp16 ctx
    flash_attn<<<dim3(8, 64), 256, SMFA>>>(
        qh, kh, vth, mask, cxh);

    // 5) out proj + residual(x)
    mma_gemm<128,3><<<dim3(8, 32, 1), 256, SM128>>>(
        cxh, Woh, bo, Dm,
        x, Dm, r1, nullptr,
        nullptr, nullptr, nullptr);

    // 6) LN1 (+ fp16 h)
    layernorm_k<true><<<MTOT, 256>>>(r1, g1, be1, hbf, hhi);

    // 7) FFN1 + relu -> fp16 f1
    mma_gemm<128,4><<<dim3(32, 32, 1), 256, SM128>>>(
        hhi, W1h, b1, Dm,
        nullptr, FFNm, nullptr, f1h,
        nullptr, nullptr, nullptr);

    // 8) FFN2 + residual(h)
    mma_gemm<128,5><<<dim3(8, 32, 1), 256, SM128>>>(
        f1h, W2h, b2, FFNm,
        hbf, Dm, r2, nullptr,
        nullptr, nullptr, nullptr);

    // 9) LN2 -> output
    layernorm_k<false><<<MTOT, 256>>>(r2, g2, be2, out, nullptr);
}

// round 8
// speedup vs baseline: 6.8834x; 1.1278x over previous
#include <cuda_runtime.h>
#include <cuda_fp16.h>
#include <cstdint>

// ---------------------------------------------------------------------------
// EncoderLayer via legacy tensor cores (mma.sync m16n8k16 fp16, f32 acc).
// Round 8: 2 CTAs/SM everywhere — GEMM reg-capped via launch_bounds(256,2),
// flash restructured to 64-key blocks (56KB smem, ~120 regs).
// B=4, S=1024, D=1024, H=16, hd=64, FFN=4096.
// ---------------------------------------------------------------------------

#define Dm   1024
#define Hh   16
#define HD   64
#define FFNm 4096
#define Bb   4
#define Ss   1024
#define MTOT (Bb*Ss)
#define NEGV (-1e9f)
#define EPSV (1e-12f)

// ------------------------------ ptx helpers -------------------------------
__device__ __forceinline__ uint32_t smem_u32(const void* p) {
    uint32_t a;
    asm("{ .reg .u64 t; cvta.to.shared.u64 t, %1; cvt.u32.u64 %0, t; }"
        : "=r"(a) : "l"(p));
    return a;
}

#define CP16(dst, src) \
    asm volatile("cp.async.cg.shared.global [%0], [%1], 16;" :: "r"(dst), "l"(src))
#define CP_COMMIT() asm volatile("cp.async.commit_group;" ::: "memory")
#define CP_WAIT1()  asm volatile("cp.async.wait_group 1;" ::: "memory")

#define LDSM4(r, addr) \
    asm volatile("ldmatrix.sync.aligned.m8n8.x4.shared.b16 {%0,%1,%2,%3}, [%4];" \
        : "=r"((r)[0]), "=r"((r)[1]), "=r"((r)[2]), "=r"((r)[3]) : "r"(addr))

#define MMA(c, a, b) \
    asm volatile("mma.sync.aligned.m16n8k16.row.col.f32.f16.f16.f32 " \
        "{%0,%1,%2,%3},{%4,%5,%6,%7},{%8,%9},{%0,%1,%2,%3};" \
        : "+f"((c)[0]), "+f"((c)[1]), "+f"((c)[2]), "+f"((c)[3]) \
        : "r"((a)[0]), "r"((a)[1]), "r"((a)[2]), "r"((a)[3]), "r"((b)[0]), "r"((b)[1]))

// ------------------------------- scratch ----------------------------------
__device__ __half g_xh[MTOT*Dm];
__device__ __half g_Wqkvh[3*Dm*Dm];
__device__ __half g_Woh[Dm*Dm];
__device__ __half g_W1h[FFNm*Dm];
__device__ __half g_W2h[Dm*FFNm];
__device__ __half g_qh[Bb*Hh*Ss*HD];
__device__ __half g_kh[Bb*Hh*Ss*HD];
__device__ __half g_vth[Bb*Hh*Ss*HD];                       // [z][d][s]
__device__ __half g_ctxh[MTOT*Dm];
__device__ float  g_r1[MTOT*Dm];
__device__ float  g_h[MTOT*Dm];
__device__ __half g_hh[MTOT*Dm];
__device__ __half g_f1h[(size_t)MTOT*FFNm];
__device__ float  g_r2[MTOT*Dm];

// ------------------------------- pack utils -------------------------------
__device__ __forceinline__ uint32_t packpair(float a, float b) {
    __half ha = __float2half_rn(a), hb = __float2half_rn(b);
    return (uint32_t)__half_as_ushort(ha) | ((uint32_t)__half_as_ushort(hb) << 16);
}

// ------------------------------- GEMM (HMMA) -------------------------------
// C[M,N] = A[M,K] @ B[N,K]^T; plain fp16 operands, fp32 accumulators.
// BM=128, BK=32, 256 threads = 8 warps (2 Mwarps x 4 Nwarps), 2 CTAs/SM.
// MODE 0: qkv scatter; MODE 3/5: +bias+resid -> fp32; MODE 4: relu -> fp16.
template<int BN, int MODE>
__global__ __launch_bounds__(256, 2)
void mma_gemm(const __half* __restrict__ Ah,
              const __half* __restrict__ Bh,
              const float* __restrict__ bias, int K,
              const float* __restrict__ resid,
              int Nc, float* __restrict__ Cf,
              __half* __restrict__ Ch,
              __half* __restrict__ qh, __half* __restrict__ kh,
              __half* __restrict__ vh)
{
    constexpr int A_BYTES = 128 * 80;
    constexpr int B_BYTES = BN * 80;
    constexpr int STAGE   = A_BYTES + B_BYTES;
    constexpr int WN = BN / 4;
    constexpr int NT = WN / 8;          // 4
    constexpr int NP = NT / 2;          // paired ldsm4 count

    const int tid = threadIdx.x;
    const int wid = tid >> 5, l = tid & 31;
    const int wm = wid >> 2, wn = wid & 3;
    const int m0 = blockIdx.y * 128;
    const int n0 = blockIdx.x * BN;

    extern __shared__ char dsm[];
    const uint32_t smem_base = smem_u32(dsm);

    uint32_t aoff[4];
    #pragma unroll
    for (int mt = 0; mt < 4; mt++)
        aoff[mt] = (uint32_t)((wm*64 + mt*16 + (l & 15)) * 80 + (l >> 4) * 16);
    uint32_t boff[NP];
    #pragma unroll
    for (int np = 0; np < NP; np++)
        boff[np] = (uint32_t)((wn*WN + np*16 + (l & 7) + ((l >> 4) & 1) * 8) * 80
                              + ((l >> 3) & 1) * 16);

    float acc[4][NT][4];
    #pragma unroll
    for (int mt = 0; mt < 4; mt++)
        #pragma unroll
        for (int nt = 0; nt < NT; nt++)
            #pragma unroll
            for (int j = 0; j < 4; j++) acc[mt][nt][j] = 0.f;

    const int niter = K >> 5;

    auto load_stage = [&](int st, int k0) {
        uint32_t base = smem_base + st * STAGE;
        #pragma unroll
        for (int i = 0; i < 2; i++) {
            int id = tid + (i << 8);
            int r = id >> 2, c = id & 3;
            CP16(base + r * 80 + c * 16, Ah + (size_t)(m0 + r) * K + k0 + c * 8);
        }
        #pragma unroll
        for (int i = 0; i < BN / 64; i++) {
            int id = tid + (i << 8);
            int r = id >> 2, c = id & 3;
            CP16(base + A_BYTES + r * 80 + c * 16, Bh + (size_t)(n0 + r) * K + k0 + c * 8);
        }
    };

    load_stage(0, 0);  CP_COMMIT();
    if (niter > 1) load_stage(1, 32);
    CP_COMMIT();

    for (int it = 0; it < niter; it++) {
        CP_WAIT1();
        __syncthreads();

        int pf = it + 2;
        if (pf < niter) load_stage(pf % 3, pf << 5);
        CP_COMMIT();

        const uint32_t sAb = smem_base + (it % 3) * STAGE;
        const uint32_t sBb = sAb + A_BYTES;
        #pragma unroll
        for (int ks = 0; ks < 2; ks++) {
            uint32_t ah[4][4];
            #pragma unroll
            for (int mt = 0; mt < 4; mt++)
                LDSM4(ah[mt], sAb + aoff[mt] + ks * 32);
            #pragma unroll
            for (int np = 0; np < NP; np++) {
                uint32_t bq[4];
                LDSM4(bq, sBb + boff[np] + ks * 32);
                #pragma unroll
                for (int mt = 0; mt < 4; mt++) {
                    MMA(acc[mt][2*np],   ah[mt], (bq + 0));
                    MMA(acc[mt][2*np+1], ah[mt], (bq + 2));
                }
            }
        }
    }

    const int rbase = m0 + wm*64 + (l >> 2);
    const int cbase = n0 + wn*WN + 2*(l & 3);

    #pragma unroll
    for (int mt = 0; mt < 4; mt++) {
        #pragma unroll
        for (int nt = 0; nt < NT; nt++) {
            const int col = cbase + nt*8;
            #pragma unroll
            for (int half_ : {0, 1}) {
                const int row = rbase + mt*16 + half_*8;
                float v0 = acc[mt][nt][half_*2 + 0];
                float v1 = acc[mt][nt][half_*2 + 1];

                if (MODE == 0) {
                    float f0 = v0 + bias[col], f1 = v1 + bias[col + 1];
                    const int which = col >> 10;
                    const int hm = col & 1023;
                    const int hidx = hm >> 6, d = hm & 63;
                    const int b = row >> 10, s = row & 1023;
                    const int zz = (b << 4) + hidx;
                    if (which == 0) {
                        f0 *= 0.125f; f1 *= 0.125f;
                        size_t idx = ((size_t)zz * Ss + s) * 64 + d;
                        *(uint32_t*)(qh + idx) = packpair(f0, f1);
                    } else if (which == 1) {
                        size_t idx = ((size_t)zz * Ss + s) * 64 + d;
                        *(uint32_t*)(kh + idx) = packpair(f0, f1);
                    } else {
                        size_t i0 = ((size_t)zz * 64 + d) * Ss + s;
                        vh[i0]      = __float2half_rn(f0);
                        vh[i0 + Ss] = __float2half_rn(f1);
                    }
                } else if (MODE == 3 || MODE == 5) {
                    size_t idx = (size_t)row * Nc + col;
                    float2 rv = *(const float2*)(resid + idx);
                    float2 o;
                    o.x = v0 + bias[col]     + rv.x;
                    o.y = v1 + bias[col + 1] + rv.y;
                    *(float2*)(Cf + idx) = o;
                } else { // MODE 4: relu + fp16
                    size_t idx = (size_t)row * Nc + col;
                    float f0 = fmaxf(v0 + bias[col], 0.f);
                    float f1 = fmaxf(v1 + bias[col + 1], 0.f);
                    *(uint32_t*)(Ch + idx) = packpair(f0, f1);
                }
            }
        }
    }
}

// --------------------------- flash attention -------------------------------
// One CTA per (z, 128-query block), 64-key inner blocks (16 iters).
// 8 warps x 16 query rows. 56KB smem, ~120 regs -> 2 CTAs/SM.
__global__ __launch_bounds__(256, 2)
void flash_attn(const __half* __restrict__ qh_, const __half* __restrict__ kh_,
                const __half* __restrict__ vh_,
                const int* __restrict__ mask,
                __half* __restrict__ cxh)
{
    constexpr int QSTRIDE = 144;             // 64 halves + 8 pad
    constexpr int QTILE   = 128 * QSTRIDE;   // 18432 B
    constexpr int KTILE   = 64 * QSTRIDE;    // 9216 B  (64 keys x 64 d)
    constexpr int VSTRIDE = 144;             // 64 keys + 8 pad
    constexpr int VTILE   = 64 * VSTRIDE;    // 9216 B  (64 d x 64 keys)
    constexpr int NBLK    = Ss / 64;         // 16 key blocks

    const int z  = blockIdx.y;               // b*16 + h
    const int q0 = blockIdx.x * 128;
    const int b  = z >> 4, h = z & 15;
    const int tid = threadIdx.x, wid = tid >> 5, l = tid & 31;

    extern __shared__ char sm[];
    const uint32_t base = smem_u32(sm);
    const uint32_t sQh = base;
    const uint32_t sKh = sQh + QTILE;        // [2 stages]
    const uint32_t sVh = sKh + 2 * KTILE;    // [2 stages]
    int* sMask = (int*)(sm + (sVh - base) + 2 * VTILE);   // [2][64]

    const __half* qhz = qh_ + (size_t)z * Ss * 64;
    const __half* khz = kh_ + (size_t)z * Ss * 64;
    const __half* vhz = vh_ + (size_t)z * 64 * Ss;
    const int*    mz  = mask + (size_t)z * Ss;

    auto load_q = [&]() {
        #pragma unroll
        for (int i = 0; i < 4; i++) {
            int id = tid + (i << 8);
            int r = id >> 3, c = id & 7;
            CP16(sQh + r * QSTRIDE + c * 16, qhz + (size_t)(q0 + r) * 64 + c * 8);
        }
    };
    auto load_kv = [&](int blk, int st) {
        int key0 = blk * 64;
        #pragma unroll
        for (int i = 0; i < 2; i++) {        // K: 64 rows x 8 chunks
            int id = tid + (i << 8);
            int r = id >> 3, c = id & 7;
            CP16(sKh + st * KTILE + r * QSTRIDE + c * 16,
                 khz + (size_t)(key0 + r) * 64 + c * 8);
        }
        #pragma unroll
        for (int i = 0; i < 2; i++) {        // V: 64 d-rows x 8 chunks (64 keys)
            int id = tid + (i << 8);
            int r = id >> 3, c = id & 7;
            CP16(sVh + st * VTILE + r * VSTRIDE + c * 16,
                 vhz + (size_t)r * Ss + key0 + c * 8);
        }
        if (tid < 64) sMask[st * 64 + tid] = mz[key0 + tid];
    };

    load_q();
    load_kv(0, 0);
    CP_COMMIT();
    load_kv(1, 1);
    CP_COMMIT();

    uint32_t qfh[4][4];
    float o[8][4];
    #pragma unroll
    for (int nt = 0; nt < 8; nt++)
        #pragma unroll
        for (int j = 0; j < 4; j++) o[nt][j] = 0.f;
    float mA = -1e30f, mB = -1e30f, lsA = 0.f, lsB = 0.f;

    const uint32_t qrow  = (uint32_t)((wid*16 + (l & 15)) * QSTRIDE + (l >> 4) * 16);
    const uint32_t krow4 = (uint32_t)(((l & 7) + ((l >> 4) & 1) * 8) * QSTRIDE
                                      + ((l >> 3) & 1) * 16);
    const uint32_t vrow4 = (uint32_t)(((l & 7) + ((l >> 4) & 1) * 8) * VSTRIDE
                                      + ((l >> 3) & 1) * 16);

    for (int it = 0; it < NBLK; it++) {
        CP_WAIT1();
        __syncthreads();

        if (it == 0) {
            #pragma unroll
            for (int ks = 0; ks < 4; ks++)
                LDSM4(qfh[ks], sQh + qrow + ks * 32);
        }

        const int st = it & 1;
        const uint32_t kb = sKh + st * KTILE;

        // ---- S = Q K^T  (16 rows x 64 keys per warp) ----
        float s[8][4];
        #pragma unroll
        for (int nt = 0; nt < 8; nt++)
            #pragma unroll
            for (int j = 0; j < 4; j++) s[nt][j] = 0.f;

        #pragma unroll
        for (int ks = 0; ks < 4; ks++) {
            #pragma unroll
            for (int np = 0; np < 4; np++) {
                uint32_t bq[4];
                LDSM4(bq, kb + krow4 + np * 16 * QSTRIDE + ks * 32);
                MMA(s[2*np],   qfh[ks], (bq + 0));
                MMA(s[2*np+1], qfh[ks], (bq + 2));
            }
        }

        // ---- mask + online softmax (over this 64-key block) ----
        const int* mk = sMask + st * 64;
        float mxA = -1e30f, mxB = -1e30f;
        #pragma unroll
        for (int nt = 0; nt < 8; nt++) {
            int c0 = nt*8 + (l & 3)*2;
            if (!mk[c0])     { s[nt][0] = NEGV; s[nt][2] = NEGV; }
            if (!mk[c0 + 1]) { s[nt][1] = NEGV; s[nt][3] = NEGV; }
            mxA = fmaxf(mxA, fmaxf(s[nt][0], s[nt][1]));
            mxB = fmaxf(mxB, fmaxf(s[nt][2], s[nt][3]));
        }
        mxA = fmaxf(mxA, __shfl_xor_sync(0xffffffffu, mxA, 1));
        mxA = fmaxf(mxA, __shfl_xor_sync(0xffffffffu, mxA, 2));
        mxB = fmaxf(mxB, __shfl_xor_sync(0xffffffffu, mxB, 1));
        mxB = fmaxf(mxB, __shfl_xor_sync(0xffffffffu, mxB, 2));

        float mAn = fmaxf(mA, mxA), mBn = fmaxf(mB, mxB);
        float scA = __expf(mA - mAn), scB = __expf(mB - mBn);
        mA = mAn; mB = mBn;

        float sumA = 0.f, sumB = 0.f;
        #pragma unroll
        for (int nt = 0; nt < 8; nt++) {
            s[nt][0] = __expf(s[nt][0] - mAn);
            s[nt][1] = __expf(s[nt][1] - mAn);
            s[nt][2] = __expf(s[nt][2] - mBn);
            s[nt][3] = __expf(s[nt][3] - mBn);
            sumA += s[nt][0] + s[nt][1];
            sumB += s[nt][2] + s[nt][3];
        }
        sumA += __shfl_xor_sync(0xffffffffu, sumA, 1);
        sumA += __shfl_xor_sync(0xffffffffu, sumA, 2);
        sumB += __shfl_xor_sync(0xffffffffu, sumB, 1);
        sumB += __shfl_xor_sync(0xffffffffu, sumB, 2);
        lsA = lsA * scA + sumA;
        lsB = lsB * scB + sumB;

        #pragma unroll
        for (int nt = 0; nt < 8; nt++) {
            o[nt][0] *= scA; o[nt][1] *= scA;
            o[nt][2] *= scB; o[nt][3] *= scB;
        }

        // ---- O += P V^T (P packed fp16 in registers, V fp16) ----
        const uint32_t vb = sVh + st * VTILE;
        #pragma unroll
        for (int ks = 0; ks < 4; ks++) {
            uint32_t ah[4];
            ah[0] = packpair(s[2*ks][0],   s[2*ks][1]);
            ah[1] = packpair(s[2*ks][2],   s[2*ks][3]);
            ah[2] = packpair(s[2*ks+1][0], s[2*ks+1][1]);
            ah[3] = packpair(s[2*ks+1][2], s[2*ks+1][3]);
            #pragma unroll
            for (int np = 0; np < 4; np++) {
                uint32_t vq[4];
                LDSM4(vq, vb + vrow4 + np * 16 * VSTRIDE + ks * 32);
                MMA(o[2*np],   ah, (vq + 0));
                MMA(o[2*np+1], ah, (vq + 2));
            }
        }

        __syncthreads();
        if (it + 2 < NBLK) load_kv(it + 2, st);
        CP_COMMIT();
    }

    // ---- epilogue: scale by 1/lsum, fp16 ctx[b, s, h*64+d] ----
    const float invA = 1.f / lsA, invB = 1.f / lsB;
    const int rowA = (b << 10) + q0 + wid*16 + (l >> 2);
    const int rowB = rowA + 8;
    #pragma unroll
    for (int nt = 0; nt < 8; nt++) {
        const int col = (h << 6) + nt*8 + (l & 3)*2;
        *(uint32_t*)(cxh + (size_t)rowA * Dm + col) =
            packpair(o[nt][0] * invA, o[nt][1] * invA);
        *(uint32_t*)(cxh + (size_t)rowB * Dm + col) =
            packpair(o[nt][2] * invB, o[nt][3] * invB);
    }
}

// ------------------------------- aux kernels -------------------------------
// x + all four weight tensors in one launch (segments in float4 units)
__global__ __launch_bounds__(256)
void tohalf_all(const float* __restrict__ x,  __half* __restrict__ dx,
                const float* __restrict__ w0, __half* __restrict__ d0,
                const float* __restrict__ w1, __half* __restrict__ d1,
                const float* __restrict__ w2, __half* __restrict__ d2,
                const float* __restrict__ w3, __half* __restrict__ d3)
{
    constexpr int NX = MTOT*Dm/4;
    constexpr int N0 = 3*Dm*Dm/4, N1 = Dm*Dm/4, N2 = FFNm*Dm/4, N3 = Dm*FFNm/4;
    int i = blockIdx.x * 256 + threadIdx.x;
    const float* src; __half* dst; int off;
    if (i < NX)                      { src = x;  dst = dx; off = i; }
    else if (i < NX+N0)              { src = w0; dst = d0; off = i - NX; }
    else if (i < NX+N0+N1)           { src = w1; dst = d1; off = i - NX - N0; }
    else if (i < NX+N0+N1+N2)        { src = w2; dst = d2; off = i - NX - N0 - N1; }
    else if (i < NX+N0+N1+N2+N3)     { src = w3; dst = d3; off = i - NX - N0 - N1 - N2; }
    else return;
    float4 v = ((const float4*)src)[off];
    uint2 hv;
    hv.x = packpair(v.x, v.y);
    hv.y = packpair(v.z, v.w);
    ((uint2*)dst)[off] = hv;
}

__device__ __forceinline__ float blockReduceSum(float v, float* sh) {
    __syncthreads();
    int lane = threadIdx.x & 31, w = threadIdx.x >> 5;
    #pragma unroll
    for (int o = 16; o; o >>= 1) v += __shfl_xor_sync(0xffffffffu, v, o);
    if (lane == 0) sh[w] = v;
    __syncthreads();
    if (threadIdx.x == 0) {
        float s = 0.f;
        #pragma unroll
        for (int i = 0; i < 8; i++) s += sh[i];
        sh[0] = s;
    }
    __syncthreads();
    return sh[0];
}

// LayerNorm (biased variance); optionally emits fp16 copy too
template<bool EMIT16>
__global__ __launch_bounds__(256)
void layernorm_k(const float* __restrict__ in, const float* __restrict__ g,
                 const float* __restrict__ be, float* __restrict__ out,
                 __half* __restrict__ o16)
{
    size_t row = blockIdx.x;
    const float4* p = (const float4*)(in + row * Dm);
    int t = threadIdx.x;
    __shared__ float sh[8];

    float4 v = p[t];
    float s  = v.x + v.y + v.z + v.w;
    float sq = v.x*v.x + v.y*v.y + v.z*v.z + v.w*v.w;
    s  = blockReduceSum(s, sh);
    sq = blockReduceSum(sq, sh);
    float mean = s * (1.f / Dm);
    float var  = sq * (1.f / Dm) - mean * mean;
    float inv  = rsqrtf(var + EPSV);

    float4 gg = ((const float4*)g)[t];
    float4 bb = ((const float4*)be)[t];
    float4 o;
    o.x = gg.x * (v.x - mean) * inv + bb.x;
    o.y = gg.y * (v.y - mean) * inv + bb.y;
    o.z = gg.z * (v.z - mean) * inv + bb.z;
    o.w = gg.w * (v.w - mean) * inv + bb.w;
    ((float4*)(out + row * Dm))[t] = o;
    if (EMIT16) {
        uint2 hv;
        hv.x = packpair(o.x, o.y);
        hv.y = packpair(o.z, o.w);
        ((uint2*)(o16 + row * Dm))[t] = hv;
    }
}

// ------------------------------- launcher ----------------------------------
static void* symaddr(const void* sym) {
    void* p = nullptr;
    cudaGetSymbolAddress(&p, sym);
    return p;
}

extern "C" void kernel_launch(void* const* d_in, const int* in_sizes, int n_in,
                              void* d_out, int out_size)
{
    const float* x    = (const float*)d_in[0];
    const int*   mask = (const int*)  d_in[1];
    const float* Wqkv = (const float*)d_in[2];
    const float* bqkv = (const float*)d_in[3];
    const float* Wo   = (const float*)d_in[4];
    const float* bo   = (const float*)d_in[5];
    const float* W1   = (const float*)d_in[6];
    const float* b1   = (const float*)d_in[7];
    const float* W2   = (const float*)d_in[8];
    const float* b2   = (const float*)d_in[9];
    const float* g1   = (const float*)d_in[10];
    const float* be1  = (const float*)d_in[11];
    const float* g2   = (const float*)d_in[12];
    const float* be2  = (const float*)d_in[13];
    float* out = (float*)d_out;

    __half* xh  = (__half*)symaddr(g_xh);
    __half* Wqh = (__half*)symaddr(g_Wqkvh);
    __half* Woh = (__half*)symaddr(g_Woh);
    __half* W1h = (__half*)symaddr(g_W1h);
    __half* W2h = (__half*)symaddr(g_W2h);
    __half* qh  = (__half*)symaddr(g_qh);
    __half* kh  = (__half*)symaddr(g_kh);
    __half* vth = (__half*)symaddr(g_vth);
    __half* cxh = (__half*)symaddr(g_ctxh);
    float*  r1  = (float*) symaddr(g_r1);
    float*  hbf = (float*) symaddr(g_h);
    __half* hhi = (__half*)symaddr(g_hh);
    __half* f1h = (__half*)symaddr(g_f1h);
    float*  r2  = (float*) symaddr(g_r2);

    constexpr int SM128 = 3 * (128*80 + 128*80);             // 61440
    constexpr int SMFA  = 18432 + 2*9216 + 2*9216 + 512;     // 55808
    cudaFuncSetAttribute(mma_gemm<128,0>, cudaFuncAttributeMaxDynamicSharedMemorySize, SM128);
    cudaFuncSetAttribute(mma_gemm<128,3>, cudaFuncAttributeMaxDynamicSharedMemorySize, SM128);
    cudaFuncSetAttribute(mma_gemm<128,4>, cudaFuncAttributeMaxDynamicSharedMemorySize, SM128);
    cudaFuncSetAttribute(mma_gemm<128,5>, cudaFuncAttributeMaxDynamicSharedMemorySize, SM128);
    cudaFuncSetAttribute(flash_attn,      cudaFuncAttributeMaxDynamicSharedMemorySize, SMFA);

    // 0) convert x + all weights to fp16 in ONE launch
    {
        constexpr int NALL = (MTOT*Dm + 3*Dm*Dm + Dm*Dm + FFNm*Dm + Dm*FFNm) / 4;
        tohalf_all<<<(NALL + 255)/256, 256>>>(x, xh, Wqkv, Wqh, Wo, Woh, W1, W1h, W2, W2h);
    }

    // 1) QKV projection -> scatter q (scaled) / k / v (transposed)
    mma_gemm<128,0><<<dim3(24, 32, 1), 256, SM128>>>(
        xh, Wqh, bqkv, Dm,
        nullptr, 3*Dm, nullptr, nullptr,
        qh, kh, vth);

    // 2-4) fused flash attention -> fp16 ctx
    flash_attn<<<dim3(8, 64), 256, SMFA>>>(
        qh, kh, vth, mask, cxh);

    // 5) out proj + residual(x)
    mma_gemm<128,3><<<dim3(8, 32, 1), 256, SM128>>>(
        cxh, Woh, bo, Dm,
        x, Dm, r1, nullptr,
        nullptr, nullptr, nullptr);

    // 6) LN1 (+ fp16 h)
    layernorm_k<true><<<MTOT, 256>>>(r1, g1, be1, hbf, hhi);

    // 7) FFN1 + relu -> fp16 f1
    mma_gemm<128,4><<<dim3(32, 32, 1), 256, SM128>>>(
        hhi, W1h, b1, Dm,
        nullptr, FFNm, nullptr, f1h,
        nullptr, nullptr, nullptr);

    // 8) FFN2 + residual(h)
    mma_gemm<128,5><<<dim3(8, 32, 1), 256, SM128>>>(
        f1h, W2h, b2, FFNm,
        hbf, Dm, r2, nullptr,
        nullptr, nullptr, nullptr);

    // 9) LN2 -> output
    layernorm_k<false><<<MTOT, 256>>>(r2, g2, be2, out, nullptr);
}